// round 2
// baseline (speedup 1.0000x reference)
#include <cuda_runtime.h>
#include <math.h>

// Problem dims
constexpr int NB = 120;
constexpr int NT = 20;
constexpr int NL = 144;
constexpr int ND = 64;
constexpr int NH = 1024;
constexpr int NA = 256;
constexpr int NR = NL * ND;   // 9216
constexpr int NG = 4 * NH;    // 4096

// -------- scratch (device globals; no runtime allocation) --------
__device__ float g_XA[(size_t)NB * NT * NL * NA]; // 354 MB: feature @ Wxa
__device__ float g_h[NB * NH];
__device__ float g_c[NB * NH];
__device__ float g_ha[NB * NA];
__device__ float g_e[NB * NL];
__device__ float g_alpha[NB * NL];
__device__ float g_beta[NB * ND];
__device__ float g_v[NB * NR];
__device__ float g_gates[NB * NG];
__device__ float g_f0[NB * ND];

__device__ __forceinline__ float sigmoidf_(float x) {
    return 1.f / (1.f + expf(-x));
}

// ---------------- init: f0 = mean_l feature[b*T+0, l, :] ----------------
__global__ void k_f0(const float* __restrict__ feat) {
    int b = blockIdx.x, d = threadIdx.x; // 64 threads
    const float* p = feat + (size_t)b * NT * NL * ND;
    float s = 0.f;
    for (int l = 0; l < NL; l++) s += p[l * ND + d];
    g_f0[b * ND + d] = s * (1.f / NL);
}

// h0 = tanh(f0 @ Wh_w^T + Wh_b), c0 = tanh(f0 @ Wc_w^T + Wc_b)
__global__ void k_h0c0(const float* __restrict__ Wh_w, const float* __restrict__ Wh_b,
                       const float* __restrict__ Wc_w, const float* __restrict__ Wc_b) {
    __shared__ float fs[ND];
    int b = blockIdx.x;
    int j = blockIdx.y * 128 + threadIdx.x;
    if (threadIdx.x < ND) fs[threadIdx.x] = g_f0[b * ND + threadIdx.x];
    __syncthreads();
    float sh = Wh_b[j], sc = Wc_b[j];
    #pragma unroll 8
    for (int d = 0; d < ND; d++) {
        float x = fs[d];
        sh += x * Wh_w[j * ND + d];
        sc += x * Wc_w[j * ND + d];
    }
    g_h[b * NH + j] = tanhf(sh);
    g_c[b * NH + j] = tanhf(sc);
}

// ---------------- XA = feature @ Wxa   [B*T*L, 256], K=64 ----------------
// block: 32 rows x 256 cols; thread: 8 rows x 4 cols
__global__ void __launch_bounds__(256) k_xa(const float* __restrict__ feat,
                                            const float* __restrict__ Wxa) {
    __shared__ float xs[32][64];   // 8 KB
    __shared__ float ws[32][256];  // 32 KB (k-tile of 32)
    const int tid = threadIdx.x;
    const int m0 = blockIdx.x * 32;

    {   // load 32x64 feature rows (2048 floats = 512 float4)
        const float4* src = reinterpret_cast<const float4*>(feat + (size_t)m0 * ND);
        float4* dst = reinterpret_cast<float4*>(&xs[0][0]);
        dst[tid] = src[tid];
        dst[tid + 256] = src[tid + 256];
    }

    const int cg = tid & 63;   // column group: cols cg*4 .. cg*4+3
    const int rg = tid >> 6;   // 0..3 -> rows rg*8 .. rg*8+7
    float acc[8][4];
    #pragma unroll
    for (int r = 0; r < 8; r++)
        #pragma unroll
        for (int c = 0; c < 4; c++) acc[r][c] = 0.f;

    #pragma unroll
    for (int kt = 0; kt < 2; kt++) {
        __syncthreads(); // also covers xs first time; protects ws reuse
        const float4* wsrc = reinterpret_cast<const float4*>(Wxa + kt * 32 * NA);
        float4* wdst = reinterpret_cast<float4*>(&ws[0][0]);
        #pragma unroll
        for (int q = 0; q < 8; q++) wdst[tid + q * 256] = wsrc[tid + q * 256];
        __syncthreads();
        #pragma unroll
        for (int kk = 0; kk < 32; kk++) {
            float4 wv = *reinterpret_cast<const float4*>(&ws[kk][cg * 4]);
            #pragma unroll
            for (int r = 0; r < 8; r++) {
                float x = xs[rg * 8 + r][kt * 32 + kk];
                acc[r][0] += x * wv.x;
                acc[r][1] += x * wv.y;
                acc[r][2] += x * wv.z;
                acc[r][3] += x * wv.w;
            }
        }
    }
    #pragma unroll
    for (int r = 0; r < 8; r++) {
        float4 o = make_float4(acc[r][0], acc[r][1], acc[r][2], acc[r][3]);
        *reinterpret_cast<float4*>(&g_XA[(size_t)(m0 + rg * 8 + r) * NA + cg * 4]) = o;
    }
}

// ---------------- per-step kernels ----------------
// ha[b,a] = sum_k h[b,k] * Wha[k,a]
__global__ void k_ha(const float* __restrict__ Wha) {
    __shared__ float hs[NH];
    int b = blockIdx.x, a = threadIdx.x; // 256 threads
    #pragma unroll
    for (int q = 0; q < NH / 256; q++) hs[a + q * 256] = g_h[b * NH + a + q * 256];
    __syncthreads();
    float s = 0.f;
    #pragma unroll 8
    for (int k = 0; k < NH; k++) s += hs[k] * Wha[(size_t)k * NA + a];
    g_ha[b * NA + a] = s;
}

// e[b,l] = sum_a tanh(XA[bt,l,a] + ha[b,a]) * wa[a]
__global__ void k_e(const float* __restrict__ wa, int t) {
    __shared__ float red[256];
    int bl = blockIdx.x;
    int b = bl / NL, l = bl % NL;
    int a = threadIdx.x;
    size_t row = (size_t)((b * NT + t) * NL + l);
    float val = tanhf(g_XA[row * NA + a] + g_ha[b * NA + a]) * wa[a];
    red[a] = val;
    __syncthreads();
    for (int s = 128; s > 0; s >>= 1) {
        if (a < s) red[a] += red[a + s];
        __syncthreads();
    }
    if (a == 0) g_e[b * NL + l] = red[0];
}

// alpha = softmax_l(e) ; also write to output
__global__ void k_softmax(float* __restrict__ out_alp, int t) {
    __shared__ float red[256];
    int b = blockIdx.x, l = threadIdx.x;
    float v = (l < NL) ? g_e[b * NL + l] : -1e30f;
    red[l] = v;
    __syncthreads();
    for (int s = 128; s > 0; s >>= 1) {
        if (l < s) red[l] = fmaxf(red[l], red[l + s]);
        __syncthreads();
    }
    float mx = red[0];
    __syncthreads();
    float ex = (l < NL) ? expf(v - mx) : 0.f;
    red[l] = ex;
    __syncthreads();
    for (int s = 128; s > 0; s >>= 1) {
        if (l < s) red[l] += red[l + s];
        __syncthreads();
    }
    float denom = red[0];
    if (l < NL) {
        float al = ex / denom;
        g_alpha[b * NL + l] = al;
        out_alp[(size_t)(b * NT + t) * NL + l] = al;
    }
}

// beta[b,d] = sigmoid(h @ Wb + bb)
__global__ void k_beta(const float* __restrict__ Wb, const float* __restrict__ bb,
                       float* __restrict__ out_bet, int t) {
    __shared__ float hs[NH];
    int b = blockIdx.x, d = threadIdx.x; // 64 threads
    #pragma unroll
    for (int q = 0; q < NH / 64; q++) hs[d + q * 64] = g_h[b * NH + d + q * 64];
    __syncthreads();
    float s = bb[d];
    #pragma unroll 8
    for (int k = 0; k < NH; k++) s += hs[k] * Wb[(size_t)k * ND + d];
    float bt = sigmoidf_(s);
    g_beta[b * ND + d] = bt;
    out_bet[(size_t)(b * NT + t) * ND + d] = bt;
}

// v[b, l*D+d] = x * (1+alpha) * beta ; also write to output
__global__ void k_v(const float* __restrict__ feat, float* __restrict__ out_vis, int t) {
    int idx = blockIdx.x * 256 + threadIdx.x; // B*R = 1105920 exactly
    int b = idx / NR, r = idx % NR;
    int l = r / ND, d = r % ND;
    float val = feat[(size_t)(b * NT + t) * NR + r] *
                (1.f + g_alpha[b * NL + l]) * g_beta[b * ND + d];
    g_v[idx] = val;
    out_vis[(size_t)(b * NT + t) * NR + r] = val;
}

// gates init with biases
__global__ void k_ginit(const float* __restrict__ b_ih, const float* __restrict__ b_hh) {
    int idx = blockIdx.x * 256 + threadIdx.x; // B*G = 491520 exactly
    int j = idx % NG;
    g_gates[idx] = b_ih[j] + b_hh[j];
}

// C[m,n] += sum_k A[m,k]*Bm[n,k]  (A = g_v or g_h selected by `which`)
// BM=128 (covers M=120), BN=128, BK=8, 256 threads, 8x8 per thread, K-split via blockIdx.z
__global__ void __launch_bounds__(256) k_gemm_nt_atomic(
    int which, const float* __restrict__ Bm, int ldb, int kchunk) {
    __shared__ float As[8][128];
    __shared__ float Bs[8][128];
    const float* Am = which ? g_h : g_v;
    const int lda = which ? NH : NR;
    const int M = NB;

    const int tid = threadIdx.x;
    const int tx = tid % 16, ty = tid / 16;
    const int n0 = blockIdx.x * 128;
    const int k0 = blockIdx.z * kchunk;

    const int lrow = tid >> 1;
    const int lko = (tid & 1) * 4;

    float acc[8][8];
    #pragma unroll
    for (int i = 0; i < 8; i++)
        #pragma unroll
        for (int j = 0; j < 8; j++) acc[i][j] = 0.f;

    for (int kb = k0; kb < k0 + kchunk; kb += 8) {
        float4 av = make_float4(0.f, 0.f, 0.f, 0.f);
        if (lrow < M)
            av = *reinterpret_cast<const float4*>(&Am[(size_t)lrow * lda + kb + lko]);
        As[lko + 0][lrow] = av.x;
        As[lko + 1][lrow] = av.y;
        As[lko + 2][lrow] = av.z;
        As[lko + 3][lrow] = av.w;
        float4 bv = *reinterpret_cast<const float4*>(&Bm[(size_t)(n0 + lrow) * ldb + kb + lko]);
        Bs[lko + 0][lrow] = bv.x;
        Bs[lko + 1][lrow] = bv.y;
        Bs[lko + 2][lrow] = bv.z;
        Bs[lko + 3][lrow] = bv.w;
        __syncthreads();
        #pragma unroll
        for (int kk = 0; kk < 8; kk++) {
            float4 a0 = *reinterpret_cast<const float4*>(&As[kk][ty * 8]);
            float4 a1 = *reinterpret_cast<const float4*>(&As[kk][ty * 8 + 4]);
            float4 b0 = *reinterpret_cast<const float4*>(&Bs[kk][tx * 8]);
            float4 b1 = *reinterpret_cast<const float4*>(&Bs[kk][tx * 8 + 4]);
            float a[8] = {a0.x, a0.y, a0.z, a0.w, a1.x, a1.y, a1.z, a1.w};
            float bb2[8] = {b0.x, b0.y, b0.z, b0.w, b1.x, b1.y, b1.z, b1.w};
            #pragma unroll
            for (int i = 0; i < 8; i++)
                #pragma unroll
                for (int j = 0; j < 8; j++) acc[i][j] += a[i] * bb2[j];
        }
        __syncthreads();
    }
    #pragma unroll
    for (int i = 0; i < 8; i++) {
        int m = ty * 8 + i;
        if (m < M) {
            #pragma unroll
            for (int j = 0; j < 8; j++)
                atomicAdd(&g_gates[(size_t)m * NG + n0 + tx * 8 + j], acc[i][j]);
        }
    }
}

// LSTM pointwise update
__global__ void k_lstm(float* __restrict__ out_hdd, int t) {
    int idx = blockIdx.x * 256 + threadIdx.x; // B*H = 122880 exactly
    int b = idx / NH, j = idx % NH;
    const float* g = g_gates + (size_t)b * NG;
    float gi = g[j];
    float gf = g[NH + j];
    float gg = g[2 * NH + j];
    float go = g[3 * NH + j];
    float c = sigmoidf_(gf) * g_c[idx] + sigmoidf_(gi) * tanhf(gg);
    float h = sigmoidf_(go) * tanhf(c);
    g_c[idx] = c;
    g_h[idx] = h;
    out_hdd[(size_t)(b * NT + t) * NH + j] = h;
}

// ---------------- host launcher ----------------
extern "C" void kernel_launch(void* const* d_in, const int* in_sizes, int n_in,
                              void* d_out, int out_size) {
    const float* feature = (const float*)d_in[0];
    const float* Wh_w = (const float*)d_in[1];
    const float* Wh_b = (const float*)d_in[2];
    const float* Wc_w = (const float*)d_in[3];
    const float* Wc_b = (const float*)d_in[4];
    const float* Wxa = (const float*)d_in[5];
    const float* Wha = (const float*)d_in[6];
    const float* wa = (const float*)d_in[7];
    const float* Wb = (const float*)d_in[8];
    const float* bb = (const float*)d_in[9];
    const float* W_ih = (const float*)d_in[10];
    const float* W_hh = (const float*)d_in[11];
    const float* b_ih = (const float*)d_in[12];
    const float* b_hh = (const float*)d_in[13];

    float* out = (float*)d_out;
    float* out_vis = out;
    float* out_hdd = out_vis + (size_t)NB * NT * NR;
    float* out_alp = out_hdd + (size_t)NB * NT * NH;
    float* out_bet = out_alp + (size_t)NB * NT * NL;

    // t-independent precompute
    k_f0<<<NB, ND>>>(feature);
    k_h0c0<<<dim3(NB, NH / 128), 128>>>(Wh_w, Wh_b, Wc_w, Wc_b);
    k_xa<<<(NB * NT * NL) / 32, 256>>>(feature, Wxa);

    for (int t = 0; t < NT; t++) {
        k_ha<<<NB, 256>>>(Wha);
        k_e<<<NB * NL, 256>>>(wa, t);
        k_softmax<<<NB, 256>>>(out_alp, t);
        k_beta<<<NB, ND>>>(Wb, bb, out_bet, t);
        k_v<<<(NB * NR) / 256, 256>>>(feature, out_vis, t);
        k_ginit<<<(NB * NG) / 256, 256>>>(b_ih, b_hh);
        // big GEMM: v @ W_ih^T, K=9216, 8-way K-split (kchunk=1152)
        k_gemm_nt_atomic<<<dim3(NG / 128, 1, 8), 256>>>(0, W_ih, NR, NR / 8);
        // small GEMM: h @ W_hh^T, K=1024, 2-way K-split (kchunk=512)
        k_gemm_nt_atomic<<<dim3(NG / 128, 1, 2), 256>>>(1, W_hh, NH, NH / 2);
        k_lstm<<<(NB * NH) / 256, 256>>>(out_hdd, t);
    }
}

// round 3
// speedup vs baseline: 2.1885x; 2.1885x over previous
#include <cuda_runtime.h>
#include <cuda_bf16.h>
#include <math.h>

// Problem dims
constexpr int NB = 120;
constexpr int NT = 20;
constexpr int NL = 144;
constexpr int ND = 64;
constexpr int NH = 1024;
constexpr int NA = 256;
constexpr int NR = NL * ND;     // 9216
constexpr int NG = 4 * NH;      // 4096
constexpr int NK = NR + NH;     // 10240 (concat v|h)

// -------- scratch (device globals; no runtime allocation) --------
__device__ float g_XA[(size_t)NB * NT * NL * NA]; // 354 MB: feature @ Wxa
__device__ float g_h[NB * NH];
__device__ float g_c[NB * NH];
__device__ float g_ha[NB * NA];
__device__ float g_e[NB * NL];
__device__ float g_alpha[NB * NL];
__device__ float g_beta[NB * ND];
__device__ float g_gates[NB * NG];
__device__ float g_f0[NB * ND];
// bf16 hi/lo operands for tensor-core GEMM (rows padded to 128, zero-init)
__device__ __nv_bfloat16 g_Ahi[128 * NK];
__device__ __nv_bfloat16 g_Alo[128 * NK];
__device__ __nv_bfloat16 g_Whi[(size_t)NG * NK];
__device__ __nv_bfloat16 g_Wlo[(size_t)NG * NK];

__device__ __forceinline__ float sigmoidf_(float x) {
    return 1.f / (1.f + expf(-x));
}

__device__ __forceinline__ void split_bf16(float x, __nv_bfloat16& hi, __nv_bfloat16& lo) {
    hi = __float2bfloat16(x);
    lo = __float2bfloat16(x - __bfloat162float(hi));
}

__device__ __forceinline__ void cp_async16(void* smem_dst, const void* gmem_src) {
    unsigned sa = (unsigned)__cvta_generic_to_shared(smem_dst);
    asm volatile("cp.async.cg.shared.global [%0], [%1], 16;\n" :: "r"(sa), "l"(gmem_src));
}

// ---------------- init: f0 = mean_l feature[b*T+0, l, :] ----------------
__global__ void k_f0(const float* __restrict__ feat) {
    int b = blockIdx.x, d = threadIdx.x; // 64 threads
    const float* p = feat + (size_t)b * NT * NL * ND;
    float s = 0.f;
    for (int l = 0; l < NL; l++) s += p[l * ND + d];
    g_f0[b * ND + d] = s * (1.f / NL);
}

// h0 = tanh(f0 @ Wh_w^T + Wh_b), c0 = tanh(f0 @ Wc_w^T + Wc_b)
__global__ void k_h0c0(const float* __restrict__ Wh_w, const float* __restrict__ Wh_b,
                       const float* __restrict__ Wc_w, const float* __restrict__ Wc_b) {
    __shared__ float fs[ND];
    int b = blockIdx.x;
    int j = blockIdx.y * 128 + threadIdx.x;
    if (threadIdx.x < ND) fs[threadIdx.x] = g_f0[b * ND + threadIdx.x];
    __syncthreads();
    float sh = Wh_b[j], sc = Wc_b[j];
    #pragma unroll 8
    for (int d = 0; d < ND; d++) {
        float x = fs[d];
        sh += x * Wh_w[j * ND + d];
        sc += x * Wc_w[j * ND + d];
    }
    float h = tanhf(sh);
    g_h[b * NH + j] = h;
    g_c[b * NH + j] = tanhf(sc);
    __nv_bfloat16 hi, lo;
    split_bf16(h, hi, lo);
    g_Ahi[b * NK + NR + j] = hi;
    g_Alo[b * NK + NR + j] = lo;
}

// split W = [W_ih | W_hh] into bf16 hi/lo   [NG][NK]
__global__ void k_wsplit(const float* __restrict__ W_ih, const float* __restrict__ W_hh) {
    size_t idx = (size_t)blockIdx.x * 256 + threadIdx.x; // NG*NK = 41.9M exactly
    int n = (int)(idx / NK), k = (int)(idx % NK);
    float x = (k < NR) ? W_ih[(size_t)n * NR + k] : W_hh[(size_t)n * NH + (k - NR)];
    __nv_bfloat16 hi, lo;
    split_bf16(x, hi, lo);
    g_Whi[idx] = hi;
    g_Wlo[idx] = lo;
}

// ---------------- XA = feature @ Wxa   [B*T*L, 256], K=64 ----------------
__global__ void __launch_bounds__(256) k_xa(const float* __restrict__ feat,
                                            const float* __restrict__ Wxa) {
    __shared__ float xs[32][64];
    __shared__ float ws[32][256];
    const int tid = threadIdx.x;
    const int m0 = blockIdx.x * 32;

    {
        const float4* src = reinterpret_cast<const float4*>(feat + (size_t)m0 * ND);
        float4* dst = reinterpret_cast<float4*>(&xs[0][0]);
        dst[tid] = src[tid];
        dst[tid + 256] = src[tid + 256];
    }

    const int cg = tid & 63;
    const int rg = tid >> 6;
    float acc[8][4];
    #pragma unroll
    for (int r = 0; r < 8; r++)
        #pragma unroll
        for (int c = 0; c < 4; c++) acc[r][c] = 0.f;

    #pragma unroll
    for (int kt = 0; kt < 2; kt++) {
        __syncthreads();
        const float4* wsrc = reinterpret_cast<const float4*>(Wxa + kt * 32 * NA);
        float4* wdst = reinterpret_cast<float4*>(&ws[0][0]);
        #pragma unroll
        for (int q = 0; q < 8; q++) wdst[tid + q * 256] = wsrc[tid + q * 256];
        __syncthreads();
        #pragma unroll
        for (int kk = 0; kk < 32; kk++) {
            float4 wv = *reinterpret_cast<const float4*>(&ws[kk][cg * 4]);
            #pragma unroll
            for (int r = 0; r < 8; r++) {
                float x = xs[rg * 8 + r][kt * 32 + kk];
                acc[r][0] += x * wv.x;
                acc[r][1] += x * wv.y;
                acc[r][2] += x * wv.z;
                acc[r][3] += x * wv.w;
            }
        }
    }
    #pragma unroll
    for (int r = 0; r < 8; r++) {
        float4 o = make_float4(acc[r][0], acc[r][1], acc[r][2], acc[r][3]);
        *reinterpret_cast<float4*>(&g_XA[(size_t)(m0 + rg * 8 + r) * NA + cg * 4]) = o;
    }
}

// ---------------- per-step kernels ----------------
// ha[b,a] = sum_k h[b,k] * Wha[k,a]   — K split across 4 groups
__global__ void __launch_bounds__(1024) k_ha(const float* __restrict__ Wha) {
    __shared__ float hs[NH];
    __shared__ float part[4][NA];
    int b = blockIdx.x;
    int tid = threadIdx.x;
    int a = tid & 255, q = tid >> 8; // q in 0..3
    hs[tid] = g_h[b * NH + tid];
    __syncthreads();
    float s = 0.f;
    int k0 = q * 256;
    #pragma unroll 16
    for (int k = 0; k < 256; k++) s += hs[k0 + k] * Wha[(size_t)(k0 + k) * NA + a];
    part[q][a] = s;
    __syncthreads();
    if (q == 0) g_ha[b * NA + a] = part[0][a] + part[1][a] + part[2][a] + part[3][a];
}

// e[b,l] = sum_a tanh(XA[bt,l,a] + ha[b,a]) * wa[a]
__global__ void k_e(const float* __restrict__ wa, int t) {
    __shared__ float red[8];
    int bl = blockIdx.x;
    int b = bl / NL, l = bl % NL;
    int a = threadIdx.x;
    size_t row = (size_t)((b * NT + t) * NL + l);
    float val = tanhf(g_XA[row * NA + a] + g_ha[b * NA + a]) * wa[a];
    #pragma unroll
    for (int o = 16; o > 0; o >>= 1) val += __shfl_xor_sync(0xffffffffu, val, o);
    if ((a & 31) == 0) red[a >> 5] = val;
    __syncthreads();
    if (a == 0) {
        float s = 0.f;
        #pragma unroll
        for (int w = 0; w < 8; w++) s += red[w];
        g_e[b * NL + l] = s;
    }
}

// alpha = softmax_l(e) ; also write to output
__global__ void k_softmax(float* __restrict__ out_alp, int t) {
    __shared__ float red[256];
    int b = blockIdx.x, l = threadIdx.x;
    float v = (l < NL) ? g_e[b * NL + l] : -1e30f;
    red[l] = v;
    __syncthreads();
    for (int s = 128; s > 0; s >>= 1) {
        if (l < s) red[l] = fmaxf(red[l], red[l + s]);
        __syncthreads();
    }
    float mx = red[0];
    __syncthreads();
    float ex = (l < NL) ? expf(v - mx) : 0.f;
    red[l] = ex;
    __syncthreads();
    for (int s = 128; s > 0; s >>= 1) {
        if (l < s) red[l] += red[l + s];
        __syncthreads();
    }
    float denom = red[0];
    if (l < NL) {
        float al = ex / denom;
        g_alpha[b * NL + l] = al;
        out_alp[(size_t)(b * NT + t) * NL + l] = al;
    }
}

// beta[b,d] = sigmoid(h @ Wb + bb)  — K split across 8 groups
__global__ void __launch_bounds__(512) k_beta(const float* __restrict__ Wb, const float* __restrict__ bb,
                                              float* __restrict__ out_bet, int t) {
    __shared__ float hs[NH];
    __shared__ float part[8][ND];
    int b = blockIdx.x;
    int tid = threadIdx.x;
    int d = tid & 63, q = tid >> 6; // q in 0..7
    hs[tid] = g_h[b * NH + tid];
    hs[tid + 512] = g_h[b * NH + tid + 512];
    __syncthreads();
    float s = 0.f;
    int k0 = q * 128;
    #pragma unroll 16
    for (int k = 0; k < 128; k++) s += hs[k0 + k] * Wb[(size_t)(k0 + k) * ND + d];
    part[q][d] = s;
    __syncthreads();
    if (q == 0) {
        float tot = bb[d];
        #pragma unroll
        for (int i = 0; i < 8; i++) tot += part[i][d];
        float bt = sigmoidf_(tot);
        g_beta[b * ND + d] = bt;
        out_bet[(size_t)(b * NT + t) * ND + d] = bt;
    }
}

// v = x*(1+alpha)*beta -> out_vis (fp32) + A hi/lo (bf16)
__global__ void k_v(const float* __restrict__ feat, float* __restrict__ out_vis, int t) {
    int idx = blockIdx.x * 256 + threadIdx.x; // B*R = 1105920 exactly
    int b = idx / NR, r = idx % NR;
    int l = r / ND, d = r % ND;
    float val = feat[(size_t)(b * NT + t) * NR + r] *
                (1.f + g_alpha[b * NL + l]) * g_beta[b * ND + d];
    out_vis[(size_t)(b * NT + t) * NR + r] = val;
    __nv_bfloat16 hi, lo;
    split_bf16(val, hi, lo);
    g_Ahi[b * NK + r] = hi;
    g_Alo[b * NK + r] = lo;
}

// gates init with biases
__global__ void k_ginit(const float* __restrict__ b_ih, const float* __restrict__ b_hh) {
    int idx = blockIdx.x * 256 + threadIdx.x; // B*G = 491520 exactly
    int j = idx % NG;
    g_gates[idx] = b_ih[j] + b_hh[j];
}

// ---------------- tensor-core GEMM: gates += A[128,10240] @ W[4096,10240]^T ----------------
// hi/lo 3-pass: acc += Ahi*Whi + Ahi*Wlo + Alo*Whi.
// BM=128, BN=64, BK=16, 8 warps (32x32 warp tiles), cp.async double buffer, KSPLIT via blockIdx.y.
constexpr int KSPLIT = 2;
constexpr int KPER = NK / KSPLIT;   // 5120
constexpr int BK = 16;
constexpr int NITER = KPER / BK;    // 320
constexpr int SSTR = 24;            // smem row stride (elements), 48B -> 16B-aligned chunks

__global__ void __launch_bounds__(256) k_mma() {
    __shared__ __nv_bfloat16 sA[2][2][128 * SSTR]; // [stage][hi/lo]
    __shared__ __nv_bfloat16 sW[2][2][64 * SSTR];

    const int tid = threadIdx.x;
    const int wid = tid >> 5, lane = tid & 31;
    const int warp_m = (wid & 3) * 32;
    const int warp_n = (wid >> 2) * 32;
    const int n0 = blockIdx.x * 64;
    const int kbase = blockIdx.y * KPER;

    // chunk mapping for cp.async (16B = 8 bf16)
    // A: 512 chunks: arr = c&1, kc = (c>>1)&1, row = c>>2
    // W: 256 chunks: same for 64 rows
    const int a_arr0 = tid & 1, a_kc0 = (tid >> 1) & 1, a_row0 = tid >> 2;

    auto issue = [&](int stage, int kt) {
        int kg = kbase + kt * BK;
        #pragma unroll
        for (int j = 0; j < 2; j++) {
            int row = a_row0 + j * 64;
            const __nv_bfloat16* src = (a_arr0 ? g_Alo : g_Ahi) + (size_t)row * NK + kg + a_kc0 * 8;
            cp_async16(&sA[stage][a_arr0][row * SSTR + a_kc0 * 8], src);
        }
        {
            const __nv_bfloat16* src = (a_arr0 ? g_Wlo : g_Whi) +
                (size_t)(n0 + a_row0) * NK + kg + a_kc0 * 8;
            cp_async16(&sW[stage][a_arr0][a_row0 * SSTR + a_kc0 * 8], src);
        }
        asm volatile("cp.async.commit_group;\n");
    };

    float acc[2][4][4];
    #pragma unroll
    for (int mi = 0; mi < 2; mi++)
        #pragma unroll
        for (int ni = 0; ni < 4; ni++)
            #pragma unroll
            for (int c = 0; c < 4; c++) acc[mi][ni][c] = 0.f;

    const int g = lane >> 2;
    const int kq = (lane & 3) * 2;

    issue(0, 0);

    for (int kt = 0; kt < NITER; kt++) {
        int stage = kt & 1;
        if (kt + 1 < NITER) {
            issue(stage ^ 1, kt + 1);
            asm volatile("cp.async.wait_group 1;\n");
        } else {
            asm volatile("cp.async.wait_group 0;\n");
        }
        __syncthreads();

        // load fragments
        unsigned ahi[2][4], alo[2][4], bhi[4][2], blo[4][2];
        #pragma unroll
        for (int mi = 0; mi < 2; mi++) {
            int rb = warp_m + mi * 16;
            const __nv_bfloat16* ph = &sA[stage][0][0];
            const __nv_bfloat16* pl = &sA[stage][1][0];
            ahi[mi][0] = *(const unsigned*)&ph[(rb + g) * SSTR + kq];
            ahi[mi][1] = *(const unsigned*)&ph[(rb + g + 8) * SSTR + kq];
            ahi[mi][2] = *(const unsigned*)&ph[(rb + g) * SSTR + kq + 8];
            ahi[mi][3] = *(const unsigned*)&ph[(rb + g + 8) * SSTR + kq + 8];
            alo[mi][0] = *(const unsigned*)&pl[(rb + g) * SSTR + kq];
            alo[mi][1] = *(const unsigned*)&pl[(rb + g + 8) * SSTR + kq];
            alo[mi][2] = *(const unsigned*)&pl[(rb + g) * SSTR + kq + 8];
            alo[mi][3] = *(const unsigned*)&pl[(rb + g + 8) * SSTR + kq + 8];
        }
        #pragma unroll
        for (int ni = 0; ni < 4; ni++) {
            int rn = warp_n + ni * 8 + g;
            const __nv_bfloat16* ph = &sW[stage][0][0];
            const __nv_bfloat16* pl = &sW[stage][1][0];
            bhi[ni][0] = *(const unsigned*)&ph[rn * SSTR + kq];
            bhi[ni][1] = *(const unsigned*)&ph[rn * SSTR + kq + 8];
            blo[ni][0] = *(const unsigned*)&pl[rn * SSTR + kq];
            blo[ni][1] = *(const unsigned*)&pl[rn * SSTR + kq + 8];
        }

        #pragma unroll
        for (int mi = 0; mi < 2; mi++) {
            #pragma unroll
            for (int ni = 0; ni < 4; ni++) {
                float* c = acc[mi][ni];
                #define MMA(AV, BV) \
                    asm volatile( \
                        "mma.sync.aligned.m16n8k16.row.col.f32.bf16.bf16.f32 " \
                        "{%0,%1,%2,%3}, {%4,%5,%6,%7}, {%8,%9}, {%0,%1,%2,%3};\n" \
                        : "+f"(c[0]), "+f"(c[1]), "+f"(c[2]), "+f"(c[3]) \
                        : "r"(AV[0]), "r"(AV[1]), "r"(AV[2]), "r"(AV[3]), \
                          "r"(BV[0]), "r"(BV[1]))
                MMA(ahi[mi], bhi[ni]);
                MMA(ahi[mi], blo[ni]);
                MMA(alo[mi], bhi[ni]);
                #undef MMA
            }
        }
        __syncthreads();
    }

    // epilogue: atomic accumulate into gates
    #pragma unroll
    for (int mi = 0; mi < 2; mi++) {
        #pragma unroll
        for (int ni = 0; ni < 4; ni++) {
            int r0 = warp_m + mi * 16 + g;
            int col = n0 + warp_n + ni * 8 + (lane & 3) * 2;
            if (r0 < NB) {
                atomicAdd(&g_gates[(size_t)r0 * NG + col], acc[mi][ni][0]);
                atomicAdd(&g_gates[(size_t)r0 * NG + col + 1], acc[mi][ni][1]);
            }
            int r1 = r0 + 8;
            if (r1 < NB) {
                atomicAdd(&g_gates[(size_t)r1 * NG + col], acc[mi][ni][2]);
                atomicAdd(&g_gates[(size_t)r1 * NG + col + 1], acc[mi][ni][3]);
            }
        }
    }
}

// LSTM pointwise update
__global__ void k_lstm(float* __restrict__ out_hdd, int t) {
    int idx = blockIdx.x * 256 + threadIdx.x; // B*H = 122880 exactly
    int b = idx / NH, j = idx % NH;
    const float* gp = g_gates + (size_t)b * NG;
    float gi = gp[j];
    float gf = gp[NH + j];
    float gg = gp[2 * NH + j];
    float go = gp[3 * NH + j];
    float c = sigmoidf_(gf) * g_c[idx] + sigmoidf_(gi) * tanhf(gg);
    float h = sigmoidf_(go) * tanhf(c);
    g_c[idx] = c;
    g_h[idx] = h;
    out_hdd[(size_t)(b * NT + t) * NH + j] = h;
    __nv_bfloat16 hi, lo;
    split_bf16(h, hi, lo);
    g_Ahi[b * NK + NR + j] = hi;
    g_Alo[b * NK + NR + j] = lo;
}

// ---------------- host launcher ----------------
extern "C" void kernel_launch(void* const* d_in, const int* in_sizes, int n_in,
                              void* d_out, int out_size) {
    const float* feature = (const float*)d_in[0];
    const float* Wh_w = (const float*)d_in[1];
    const float* Wh_b = (const float*)d_in[2];
    const float* Wc_w = (const float*)d_in[3];
    const float* Wc_b = (const float*)d_in[4];
    const float* Wxa = (const float*)d_in[5];
    const float* Wha = (const float*)d_in[6];
    const float* wa = (const float*)d_in[7];
    const float* Wb = (const float*)d_in[8];
    const float* bb = (const float*)d_in[9];
    const float* W_ih = (const float*)d_in[10];
    const float* W_hh = (const float*)d_in[11];
    const float* b_ih = (const float*)d_in[12];
    const float* b_hh = (const float*)d_in[13];

    float* out = (float*)d_out;
    float* out_vis = out;
    float* out_hdd = out_vis + (size_t)NB * NT * NR;
    float* out_alp = out_hdd + (size_t)NB * NT * NH;
    float* out_bet = out_alp + (size_t)NB * NT * NL;

    // t-independent precompute
    k_f0<<<NB, ND>>>(feature);
    k_h0c0<<<dim3(NB, NH / 128), 128>>>(Wh_w, Wh_b, Wc_w, Wc_b);
    k_wsplit<<<(int)(((size_t)NG * NK) / 256), 256>>>(W_ih, W_hh);
    k_xa<<<(NB * NT * NL) / 32, 256>>>(feature, Wxa);

    for (int t = 0; t < NT; t++) {
        k_ha<<<NB, 1024>>>(Wha);
        k_e<<<NB * NL, 256>>>(wa, t);
        k_softmax<<<NB, 256>>>(out_alp, t);
        k_beta<<<NB, 512>>>(Wb, bb, out_bet, t);
        k_v<<<(NB * NR) / 256, 256>>>(feature, out_vis, t);
        k_ginit<<<(NB * NG) / 256, 256>>>(b_ih, b_hh);
        k_mma<<<dim3(NG / 64, KSPLIT), 256>>>();
        k_lstm<<<(NB * NH) / 256, 256>>>(out_hdd, t);
    }
}

// round 4
// speedup vs baseline: 3.1917x; 1.4584x over previous
#include <cuda_runtime.h>
#include <cuda_bf16.h>
#include <math.h>

// Problem dims
constexpr int NB = 120;
constexpr int NT = 20;
constexpr int NL = 144;
constexpr int ND = 64;
constexpr int NH = 1024;
constexpr int NA = 256;
constexpr int NR = NL * ND;     // 9216
constexpr int NG = 4 * NH;      // 4096
constexpr int NK = NR + NH;     // 10240 (concat v|h)

// GEMM config
constexpr int KSPLIT = 4;
constexpr int KPER = NK / KSPLIT;   // 2560
constexpr int BK = 32;
constexpr int NIT = KPER / BK;      // 80
constexpr int SSTR = 40;            // padded smem row stride (bf16 elems)
constexpr int STG_ELEMS = 2 * (128 * SSTR) + 2 * (128 * SSTR); // A(2 arr) + W(2 arr) = 20480
constexpr int SMEM_BYTES = 3 * STG_ELEMS * 2;                  // 3 stages = 122880 B

// -------- scratch (device globals; no runtime allocation) --------
__device__ float g_XA[(size_t)NB * NT * NL * NA]; // 354 MB: feature @ Wxa
__device__ float g_h[NB * NH];
__device__ float g_c[NB * NH];
__device__ float g_ha[NB * NA];
__device__ float g_e[NB * NL];
__device__ float g_alpha[NB * NL];
__device__ float g_beta[NB * ND];
__device__ float g_f0[NB * ND];
__device__ float g_gp[KSPLIT][NB * NG];   // per-K-split GEMM partials
// bf16 hi/lo operands (rows padded to 128; .bss zero-init keeps pad rows zero)
__device__ __align__(16) __nv_bfloat16 g_Ahi[128 * NK];
__device__ __align__(16) __nv_bfloat16 g_Alo[128 * NK];
__device__ __align__(16) __nv_bfloat16 g_Whi[(size_t)NG * NK];
__device__ __align__(16) __nv_bfloat16 g_Wlo[(size_t)NG * NK];

__device__ __forceinline__ float sigmoidf_(float x) {
    return 1.f / (1.f + expf(-x));
}

__device__ __forceinline__ void split_bf16(float x, __nv_bfloat16& hi, __nv_bfloat16& lo) {
    hi = __float2bfloat16(x);
    lo = __float2bfloat16(x - __bfloat162float(hi));
}

__device__ __forceinline__ void cp_async16(void* smem_dst, const void* gmem_src) {
    unsigned sa = (unsigned)__cvta_generic_to_shared(smem_dst);
    asm volatile("cp.async.cg.shared.global [%0], [%1], 16;\n" :: "r"(sa), "l"(gmem_src));
}

__device__ __forceinline__ void ldsm_x4(unsigned* r, const __nv_bfloat16* p) {
    unsigned sa = (unsigned)__cvta_generic_to_shared(p);
    asm volatile("ldmatrix.sync.aligned.m8n8.x4.shared.b16 {%0,%1,%2,%3}, [%4];"
                 : "=r"(r[0]), "=r"(r[1]), "=r"(r[2]), "=r"(r[3]) : "r"(sa));
}

// ---------------- init: f0 = mean_l feature[b*T+0, l, :] ----------------
__global__ void k_f0(const float* __restrict__ feat) {
    int b = blockIdx.x, d = threadIdx.x; // 64 threads
    const float* p = feat + (size_t)b * NT * NL * ND;
    float s = 0.f;
    for (int l = 0; l < NL; l++) s += p[l * ND + d];
    g_f0[b * ND + d] = s * (1.f / NL);
}

// h0 = tanh(f0 @ Wh_w^T + Wh_b), c0 = tanh(f0 @ Wc_w^T + Wc_b)
__global__ void k_h0c0(const float* __restrict__ Wh_w, const float* __restrict__ Wh_b,
                       const float* __restrict__ Wc_w, const float* __restrict__ Wc_b) {
    __shared__ float fs[ND];
    int b = blockIdx.x;
    int j = blockIdx.y * 128 + threadIdx.x;
    if (threadIdx.x < ND) fs[threadIdx.x] = g_f0[b * ND + threadIdx.x];
    __syncthreads();
    float sh = Wh_b[j], sc = Wc_b[j];
    #pragma unroll 8
    for (int d = 0; d < ND; d++) {
        float x = fs[d];
        sh += x * Wh_w[j * ND + d];
        sc += x * Wc_w[j * ND + d];
    }
    float h = tanhf(sh);
    g_h[b * NH + j] = h;
    g_c[b * NH + j] = tanhf(sc);
    __nv_bfloat16 hi, lo;
    split_bf16(h, hi, lo);
    g_Ahi[b * NK + NR + j] = hi;
    g_Alo[b * NK + NR + j] = lo;
}

// split W = [W_ih | W_hh] into bf16 hi/lo   [NG][NK]
__global__ void k_wsplit(const float* __restrict__ W_ih, const float* __restrict__ W_hh) {
    size_t idx = (size_t)blockIdx.x * 256 + threadIdx.x; // NG*NK exactly
    int n = (int)(idx / NK), k = (int)(idx % NK);
    float x = (k < NR) ? W_ih[(size_t)n * NR + k] : W_hh[(size_t)n * NH + (k - NR)];
    __nv_bfloat16 hi, lo;
    split_bf16(x, hi, lo);
    g_Whi[idx] = hi;
    g_Wlo[idx] = lo;
}

// ---------------- XA = feature @ Wxa   [B*T*L, 256], K=64 ----------------
__global__ void __launch_bounds__(256) k_xa(const float* __restrict__ feat,
                                            const float* __restrict__ Wxa) {
    __shared__ float xs[32][64];
    __shared__ float ws[32][256];
    const int tid = threadIdx.x;
    const int m0 = blockIdx.x * 32;

    {
        const float4* src = reinterpret_cast<const float4*>(feat + (size_t)m0 * ND);
        float4* dst = reinterpret_cast<float4*>(&xs[0][0]);
        dst[tid] = src[tid];
        dst[tid + 256] = src[tid + 256];
    }

    const int cg = tid & 63;
    const int rg = tid >> 6;
    float acc[8][4];
    #pragma unroll
    for (int r = 0; r < 8; r++)
        #pragma unroll
        for (int c = 0; c < 4; c++) acc[r][c] = 0.f;

    #pragma unroll
    for (int kt = 0; kt < 2; kt++) {
        __syncthreads();
        const float4* wsrc = reinterpret_cast<const float4*>(Wxa + kt * 32 * NA);
        float4* wdst = reinterpret_cast<float4*>(&ws[0][0]);
        #pragma unroll
        for (int q = 0; q < 8; q++) wdst[tid + q * 256] = wsrc[tid + q * 256];
        __syncthreads();
        #pragma unroll
        for (int kk = 0; kk < 32; kk++) {
            float4 wv = *reinterpret_cast<const float4*>(&ws[kk][cg * 4]);
            #pragma unroll
            for (int r = 0; r < 8; r++) {
                float x = xs[rg * 8 + r][kt * 32 + kk];
                acc[r][0] += x * wv.x;
                acc[r][1] += x * wv.y;
                acc[r][2] += x * wv.z;
                acc[r][3] += x * wv.w;
            }
        }
    }
    #pragma unroll
    for (int r = 0; r < 8; r++) {
        float4 o = make_float4(acc[r][0], acc[r][1], acc[r][2], acc[r][3]);
        *reinterpret_cast<float4*>(&g_XA[(size_t)(m0 + rg * 8 + r) * NA + cg * 4]) = o;
    }
}

// ---------------- per-step kernels ----------------
// fused: ha = h @ Wha (K-split x4) and beta = sigmoid(h @ Wb + bb) (K-split x8)
__global__ void __launch_bounds__(1024) k_hb(const float* __restrict__ Wha,
                                             const float* __restrict__ Wb,
                                             const float* __restrict__ bb,
                                             float* __restrict__ out_bet, int t) {
    __shared__ float hs[NH];
    __shared__ float pa[4][NA];
    __shared__ float pb[8][ND];
    int b = blockIdx.x, tid = threadIdx.x;
    hs[tid] = g_h[b * NH + tid];
    __syncthreads();
    {
        int a = tid & 255, q = tid >> 8;
        int k0 = q * 256;
        float s = 0.f;
        #pragma unroll 16
        for (int k = 0; k < 256; k++) s += hs[k0 + k] * Wha[(size_t)(k0 + k) * NA + a];
        pa[q][a] = s;
    }
    if (tid < 512) {
        int d = tid & 63, q = tid >> 6;
        int k0 = q * 128;
        float s = 0.f;
        #pragma unroll 16
        for (int k = 0; k < 128; k++) s += hs[k0 + k] * Wb[(size_t)(k0 + k) * ND + d];
        pb[q][d] = s;
    }
    __syncthreads();
    if (tid < 256) {
        g_ha[b * NA + tid] = pa[0][tid] + pa[1][tid] + pa[2][tid] + pa[3][tid];
    } else if (tid < 320) {
        int d = tid - 256;
        float tot = bb[d];
        #pragma unroll
        for (int i = 0; i < 8; i++) tot += pb[i][d];
        float bt = sigmoidf_(tot);
        g_beta[b * ND + d] = bt;
        out_bet[(size_t)(b * NT + t) * ND + d] = bt;
    }
}

// e[b,l] = sum_a tanh(XA[bt,l,a] + ha[b,a]) * wa[a]
__global__ void k_e(const float* __restrict__ wa, int t) {
    __shared__ float red[8];
    int bl = blockIdx.x;
    int b = bl / NL, l = bl % NL;
    int a = threadIdx.x;
    size_t row = (size_t)((b * NT + t) * NL + l);
    float val = tanhf(g_XA[row * NA + a] + g_ha[b * NA + a]) * wa[a];
    #pragma unroll
    for (int o = 16; o > 0; o >>= 1) val += __shfl_xor_sync(0xffffffffu, val, o);
    if ((a & 31) == 0) red[a >> 5] = val;
    __syncthreads();
    if (a == 0) {
        float s = 0.f;
        #pragma unroll
        for (int w = 0; w < 8; w++) s += red[w];
        g_e[b * NL + l] = s;
    }
}

// alpha = softmax_l(e) ; also write to output
__global__ void k_softmax(float* __restrict__ out_alp, int t) {
    __shared__ float red[256];
    int b = blockIdx.x, l = threadIdx.x;
    float v = (l < NL) ? g_e[b * NL + l] : -1e30f;
    red[l] = v;
    __syncthreads();
    for (int s = 128; s > 0; s >>= 1) {
        if (l < s) red[l] = fmaxf(red[l], red[l + s]);
        __syncthreads();
    }
    float mx = red[0];
    __syncthreads();
    float ex = (l < NL) ? expf(v - mx) : 0.f;
    red[l] = ex;
    __syncthreads();
    for (int s = 128; s > 0; s >>= 1) {
        if (l < s) red[l] += red[l + s];
        __syncthreads();
    }
    float denom = red[0];
    if (l < NL) {
        float al = ex / denom;
        g_alpha[b * NL + l] = al;
        out_alp[(size_t)(b * NT + t) * NL + l] = al;
    }
}

// v = x*(1+alpha)*beta -> out_vis (fp32) + A hi/lo (bf16)
__global__ void k_v(const float* __restrict__ feat, float* __restrict__ out_vis, int t) {
    int idx = blockIdx.x * 256 + threadIdx.x; // B*R = 1105920 exactly
    int b = idx / NR, r = idx % NR;
    int l = r / ND, d = r % ND;
    float val = feat[(size_t)(b * NT + t) * NR + r] *
                (1.f + g_alpha[b * NL + l]) * g_beta[b * ND + d];
    out_vis[(size_t)(b * NT + t) * NR + r] = val;
    __nv_bfloat16 hi, lo;
    split_bf16(val, hi, lo);
    g_Ahi[b * NK + r] = hi;
    g_Alo[b * NK + r] = lo;
}

// ---------------- tensor-core GEMM: gp[z] = A[128,Kz] @ W[4096,Kz]^T ----------------
// hi/lo 3-pass: acc += Ahi*Whi + Ahi*Wlo + Alo*Whi.
// BM=128, BN=128, BK=32, 8 warps (warp tile 32x64), ldmatrix.x4, 3-stage cp.async.
__global__ void __launch_bounds__(256) k_mma() {
    extern __shared__ __nv_bfloat16 smem[];

    const int tid = threadIdx.x;
    const int wid = tid >> 5, lane = tid & 31;
    const int warp_m = (wid & 3) * 32;
    const int warp_n = (wid >> 2) * 64;
    const int n0 = blockIdx.x * 128;
    const int z = blockIdx.y;
    const int kbase = z * KPER;

    // chunk decode for cp.async: per array group 1024 chunks (128 rows x 4 kc x 2 arr)
    const int c_row = tid >> 1;          // base rows handled by this thread: tid>>1 + 128*q? no:
    // We iterate q=0..3: chunk id c = tid + q*256 ; row=c>>3, kc=c&3, arr=(c>>2)&1

    auto issue = [&](int stage, int kt) {
        const int k0 = kbase + kt * BK;
        __nv_bfloat16* sA = smem + stage * STG_ELEMS;
        __nv_bfloat16* sW = sA + 2 * 128 * SSTR;
        #pragma unroll
        for (int q = 0; q < 4; q++) {
            int c = tid + q * 256;
            int row = c >> 3, kc = c & 3, arr = (c >> 2) & 1;
            const __nv_bfloat16* src = (arr ? g_Alo : g_Ahi) + (size_t)row * NK + k0 + kc * 8;
            cp_async16(sA + arr * (128 * SSTR) + row * SSTR + kc * 8, src);
        }
        #pragma unroll
        for (int q = 0; q < 4; q++) {
            int c = tid + q * 256;
            int row = c >> 3, kc = c & 3, arr = (c >> 2) & 1;
            const __nv_bfloat16* src = (arr ? g_Wlo : g_Whi) + (size_t)(n0 + row) * NK + k0 + kc * 8;
            cp_async16(sW + arr * (128 * SSTR) + row * SSTR + kc * 8, src);
        }
        asm volatile("cp.async.commit_group;\n");
    };

    float acc[2][8][4];
    #pragma unroll
    for (int mi = 0; mi < 2; mi++)
        #pragma unroll
        for (int nt = 0; nt < 8; nt++)
            #pragma unroll
            for (int c = 0; c < 4; c++) acc[mi][nt][c] = 0.f;

    issue(0, 0);
    issue(1, 1);

    // precomputed lane offsets
    const int a_row_l = lane & 15;            // row within m16 tile
    const int a_col_l = (lane >> 4) * 8;      // k-half
    const int b_row_l = (lane & 7) + ((lane >> 4) << 3); // row within n16 pair
    const int b_col_l = ((lane >> 3) & 1) * 8;           // k-half

    for (int kt = 0; kt < NIT; kt++) {
        if (kt + 2 < NIT) {
            issue((kt + 2) % 3, kt + 2);
            asm volatile("cp.async.wait_group 2;\n");
        } else if (kt + 1 < NIT) {
            asm volatile("cp.async.wait_group 1;\n");
        } else {
            asm volatile("cp.async.wait_group 0;\n");
        }
        __syncthreads();

        const __nv_bfloat16* sA = smem + (kt % 3) * STG_ELEMS;
        const __nv_bfloat16* sW = sA + 2 * 128 * SSTR;

        #pragma unroll
        for (int ks = 0; ks < 2; ks++) {
            unsigned af[2][2][4]; // [arr][mi]
            #pragma unroll
            for (int arr = 0; arr < 2; arr++)
                #pragma unroll
                for (int mi = 0; mi < 2; mi++)
                    ldsm_x4(af[arr][mi],
                            sA + arr * (128 * SSTR) +
                            (warp_m + mi * 16 + a_row_l) * SSTR + ks * 16 + a_col_l);
            unsigned bf[2][4][4]; // [arr][nj] -> {t0b0,t0b1,t1b0,t1b1}
            #pragma unroll
            for (int arr = 0; arr < 2; arr++)
                #pragma unroll
                for (int nj = 0; nj < 4; nj++)
                    ldsm_x4(bf[arr][nj],
                            sW + arr * (128 * SSTR) +
                            (warp_n + nj * 16 + b_row_l) * SSTR + ks * 16 + b_col_l);

            #pragma unroll
            for (int mi = 0; mi < 2; mi++) {
                #pragma unroll
                for (int nt = 0; nt < 8; nt++) {
                    const int nj = nt >> 1, p = (nt & 1) * 2;
                    float* c = acc[mi][nt];
                    #define MMA(AV, B0, B1) \
                        asm volatile( \
                            "mma.sync.aligned.m16n8k16.row.col.f32.bf16.bf16.f32 " \
                            "{%0,%1,%2,%3}, {%4,%5,%6,%7}, {%8,%9}, {%0,%1,%2,%3};\n" \
                            : "+f"(c[0]), "+f"(c[1]), "+f"(c[2]), "+f"(c[3]) \
                            : "r"(AV[0]), "r"(AV[1]), "r"(AV[2]), "r"(AV[3]), \
                              "r"(B0), "r"(B1))
                    MMA(af[0][mi], bf[0][nj][p], bf[0][nj][p + 1]);
                    MMA(af[0][mi], bf[1][nj][p], bf[1][nj][p + 1]);
                    MMA(af[1][mi], bf[0][nj][p], bf[0][nj][p + 1]);
                    #undef MMA
                }
            }
        }
        __syncthreads();
    }

    // epilogue: store partials (no atomics -> deterministic)
    float* gp = g_gp[z];
    const int g = lane >> 2, q2 = (lane & 3) * 2;
    #pragma unroll
    for (int mi = 0; mi < 2; mi++) {
        #pragma unroll
        for (int nt = 0; nt < 8; nt++) {
            int col = n0 + warp_n + nt * 8 + q2;
            int r0 = warp_m + mi * 16 + g;
            if (r0 < NB)
                *reinterpret_cast<float2*>(&gp[(size_t)r0 * NG + col]) =
                    make_float2(acc[mi][nt][0], acc[mi][nt][1]);
            int r1 = r0 + 8;
            if (r1 < NB)
                *reinterpret_cast<float2*>(&gp[(size_t)r1 * NG + col]) =
                    make_float2(acc[mi][nt][2], acc[mi][nt][3]);
        }
    }
}

// LSTM pointwise update (sums K-split partials + biases)
__global__ void k_lstm(const float* __restrict__ b_ih, const float* __restrict__ b_hh,
                       float* __restrict__ out_hdd, int t) {
    int idx = blockIdx.x * 256 + threadIdx.x; // B*H = 122880 exactly
    int b = idx / NH, j = idx % NH;
    float gi = b_ih[j] + b_hh[j];
    float gf = b_ih[NH + j] + b_hh[NH + j];
    float gg = b_ih[2 * NH + j] + b_hh[2 * NH + j];
    float go = b_ih[3 * NH + j] + b_hh[3 * NH + j];
    #pragma unroll
    for (int z = 0; z < KSPLIT; z++) {
        const float* gp = g_gp[z] + (size_t)b * NG;
        gi += gp[j];
        gf += gp[NH + j];
        gg += gp[2 * NH + j];
        go += gp[3 * NH + j];
    }
    float c = sigmoidf_(gf) * g_c[idx] + sigmoidf_(gi) * tanhf(gg);
    float h = sigmoidf_(go) * tanhf(c);
    g_c[idx] = c;
    g_h[idx] = h;
    out_hdd[(size_t)(b * NT + t) * NH + j] = h;
    __nv_bfloat16 hi, lo;
    split_bf16(h, hi, lo);
    g_Ahi[b * NK + NR + j] = hi;
    g_Alo[b * NK + NR + j] = lo;
}

// ---------------- host launcher ----------------
extern "C" void kernel_launch(void* const* d_in, const int* in_sizes, int n_in,
                              void* d_out, int out_size) {
    const float* feature = (const float*)d_in[0];
    const float* Wh_w = (const float*)d_in[1];
    const float* Wh_b = (const float*)d_in[2];
    const float* Wc_w = (const float*)d_in[3];
    const float* Wc_b = (const float*)d_in[4];
    const float* Wxa = (const float*)d_in[5];
    const float* Wha = (const float*)d_in[6];
    const float* wa = (const float*)d_in[7];
    const float* Wb = (const float*)d_in[8];
    const float* bb = (const float*)d_in[9];
    const float* W_ih = (const float*)d_in[10];
    const float* W_hh = (const float*)d_in[11];
    const float* b_ih = (const float*)d_in[12];
    const float* b_hh = (const float*)d_in[13];

    float* out = (float*)d_out;
    float* out_vis = out;
    float* out_hdd = out_vis + (size_t)NB * NT * NR;
    float* out_alp = out_hdd + (size_t)NB * NT * NH;
    float* out_bet = out_alp + (size_t)NB * NT * NL;

    cudaFuncSetAttribute(k_mma, cudaFuncAttributeMaxDynamicSharedMemorySize, SMEM_BYTES);

    // t-independent precompute
    k_f0<<<NB, ND>>>(feature);
    k_h0c0<<<dim3(NB, NH / 128), 128>>>(Wh_w, Wh_b, Wc_w, Wc_b);
    k_wsplit<<<(int)(((size_t)NG * NK) / 256), 256>>>(W_ih, W_hh);
    k_xa<<<(NB * NT * NL) / 32, 256>>>(feature, Wxa);

    for (int t = 0; t < NT; t++) {
        k_hb<<<NB, 1024>>>(Wha, Wb, bb, out_bet, t);
        k_e<<<NB * NL, 256>>>(wa, t);
        k_softmax<<<NB, 256>>>(out_alp, t);
        k_v<<<(NB * NR) / 256, 256>>>(feature, out_vis, t);
        k_mma<<<dim3(NG / 128, KSPLIT), 256, SMEM_BYTES>>>();
        k_lstm<<<(NB * NH) / 256, 256>>>(b_ih, b_hh, out_hdd, t);
    }
}

// round 5
// speedup vs baseline: 3.2550x; 1.0198x over previous
#include <cuda_runtime.h>
#include <cuda_bf16.h>
#include <math.h>

// Problem dims
constexpr int NB = 120;
constexpr int NT = 20;
constexpr int NL = 144;
constexpr int ND = 64;
constexpr int NH = 1024;
constexpr int NA = 256;
constexpr int NR = NL * ND;     // 9216
constexpr int NG = 4 * NH;      // 4096
constexpr int NK = NR + NH;     // 10240 (concat v|h)

// Recurrent GEMM config
constexpr int KSPLIT = 4;
constexpr int KPER = NK / KSPLIT;   // 2560
constexpr int BK = 32;
constexpr int NIT = KPER / BK;      // 80
constexpr int SSTR = 40;            // padded smem row stride (bf16 elems)
constexpr int STG_ELEMS = 2 * (128 * SSTR) + 2 * (128 * SSTR); // 20480
constexpr int SMEM_BYTES = 4 * STG_ELEMS * 2;                  // 4 stages = 163840 B

// XA GEMM config
constexpr int XA_SSTR = 72;
constexpr int XA_SMEM = (2 * 128 * XA_SSTR + 2 * 256 * XA_SSTR) * 2; // 110592 B

// -------- scratch (device globals; no runtime allocation) --------
__device__ float g_XA[(size_t)NB * NT * NL * NA]; // 354 MB: feature @ Wxa
__device__ float g_h[NB * NH];
__device__ float g_c[NB * NH];
__device__ float g_alpha[NB * NL];
__device__ float g_beta[NB * ND];
__device__ float g_f0[NB * ND];
__device__ float g_gp[KSPLIT][NB * NG];   // per-K-split GEMM partials
// bf16 hi/lo operands (.bss zero-init keeps pad rows zero)
__device__ __align__(16) __nv_bfloat16 g_Ahi[128 * NK];
__device__ __align__(16) __nv_bfloat16 g_Alo[128 * NK];
__device__ __align__(16) __nv_bfloat16 g_Whi[(size_t)NG * NK];
__device__ __align__(16) __nv_bfloat16 g_Wlo[(size_t)NG * NK];
__device__ __align__(16) __nv_bfloat16 g_Fhi[(size_t)NB * NT * NL * ND]; // feature hi/lo
__device__ __align__(16) __nv_bfloat16 g_Flo[(size_t)NB * NT * NL * ND];
__device__ __align__(16) __nv_bfloat16 g_WxaThi[NA * ND]; // Wxa^T [256][64]
__device__ __align__(16) __nv_bfloat16 g_WxaTlo[NA * ND];

__device__ __forceinline__ float sigmoidf_(float x) {
    return 1.f / (1.f + expf(-x));
}

__device__ __forceinline__ void split_bf16(float x, __nv_bfloat16& hi, __nv_bfloat16& lo) {
    hi = __float2bfloat16(x);
    lo = __float2bfloat16(x - __bfloat162float(hi));
}

__device__ __forceinline__ void cp_async16(void* smem_dst, const void* gmem_src) {
    unsigned sa = (unsigned)__cvta_generic_to_shared(smem_dst);
    asm volatile("cp.async.cg.shared.global [%0], [%1], 16;\n" :: "r"(sa), "l"(gmem_src));
}

__device__ __forceinline__ void ldsm_x4(unsigned* r, const __nv_bfloat16* p) {
    unsigned sa = (unsigned)__cvta_generic_to_shared(p);
    asm volatile("ldmatrix.sync.aligned.m8n8.x4.shared.b16 {%0,%1,%2,%3}, [%4];"
                 : "=r"(r[0]), "=r"(r[1]), "=r"(r[2]), "=r"(r[3]) : "r"(sa));
}

#define MMA_BF16(C, AV, B0, B1) \
    asm volatile( \
        "mma.sync.aligned.m16n8k16.row.col.f32.bf16.bf16.f32 " \
        "{%0,%1,%2,%3}, {%4,%5,%6,%7}, {%8,%9}, {%0,%1,%2,%3};\n" \
        : "+f"((C)[0]), "+f"((C)[1]), "+f"((C)[2]), "+f"((C)[3]) \
        : "r"((AV)[0]), "r"((AV)[1]), "r"((AV)[2]), "r"((AV)[3]), \
          "r"(B0), "r"(B1))

// ---------------- init: f0 = mean_l feature[b*T+0, l, :] ----------------
__global__ void k_f0(const float* __restrict__ feat) {
    int b = blockIdx.x, d = threadIdx.x; // 64 threads
    const float* p = feat + (size_t)b * NT * NL * ND;
    float s = 0.f;
    for (int l = 0; l < NL; l++) s += p[l * ND + d];
    g_f0[b * ND + d] = s * (1.f / NL);
}

// h0 = tanh(f0 @ Wh_w^T + Wh_b), c0 = tanh(f0 @ Wc_w^T + Wc_b)
__global__ void k_h0c0(const float* __restrict__ Wh_w, const float* __restrict__ Wh_b,
                       const float* __restrict__ Wc_w, const float* __restrict__ Wc_b) {
    __shared__ float fs[ND];
    int b = blockIdx.x;
    int j = blockIdx.y * 128 + threadIdx.x;
    if (threadIdx.x < ND) fs[threadIdx.x] = g_f0[b * ND + threadIdx.x];
    __syncthreads();
    float sh = Wh_b[j], sc = Wc_b[j];
    #pragma unroll 8
    for (int d = 0; d < ND; d++) {
        float x = fs[d];
        sh += x * Wh_w[j * ND + d];
        sc += x * Wc_w[j * ND + d];
    }
    float h = tanhf(sh);
    g_h[b * NH + j] = h;
    g_c[b * NH + j] = tanhf(sc);
    __nv_bfloat16 hi, lo;
    split_bf16(h, hi, lo);
    g_Ahi[b * NK + NR + j] = hi;
    g_Alo[b * NK + NR + j] = lo;
}

// split W = [W_ih | W_hh] into bf16 hi/lo   [NG][NK]
__global__ void k_wsplit(const float* __restrict__ W_ih, const float* __restrict__ W_hh) {
    size_t idx = (size_t)blockIdx.x * 256 + threadIdx.x; // NG*NK exactly
    int n = (int)(idx / NK), k = (int)(idx % NK);
    float x = (k < NR) ? W_ih[(size_t)n * NR + k] : W_hh[(size_t)n * NH + (k - NR)];
    __nv_bfloat16 hi, lo;
    split_bf16(x, hi, lo);
    g_Whi[idx] = hi;
    g_Wlo[idx] = lo;
}

// split feature into bf16 hi/lo
__global__ void k_fsplit(const float* __restrict__ feat) {
    size_t idx = (size_t)blockIdx.x * 256 + threadIdx.x; // NB*NT*NL*ND exactly
    __nv_bfloat16 hi, lo;
    split_bf16(feat[idx], hi, lo);
    g_Fhi[idx] = hi;
    g_Flo[idx] = lo;
}

// transpose + split Wxa [64][256] -> WxaT [256][64]
__global__ void k_wxat(const float* __restrict__ Wxa) {
    int d = blockIdx.x, a = threadIdx.x; // 64 blocks x 256 threads
    __nv_bfloat16 hi, lo;
    split_bf16(Wxa[d * NA + a], hi, lo);
    g_WxaThi[a * ND + d] = hi;
    g_WxaTlo[a * ND + d] = lo;
}

// ---------------- XA = feature @ Wxa via tensor cores ----------------
// BM=128, BN=256 (full N), K=64 one shot; 512 threads, 16 warps (warp tile 32x64).
__global__ void __launch_bounds__(512) k_xa2() {
    extern __shared__ __nv_bfloat16 xsm[];
    __nv_bfloat16* sA = xsm;                       // 2 arr x 128 x XA_SSTR
    __nv_bfloat16* sW = xsm + 2 * 128 * XA_SSTR;   // 2 arr x 256 x XA_SSTR

    const int tid = threadIdx.x;
    const int wid = tid >> 5, lane = tid & 31;
    const int m0 = blockIdx.x * 128;

    // A: 2048 chunks of 16B
    #pragma unroll
    for (int q = 0; q < 4; q++) {
        int c = tid + q * 512;
        int kc = c & 7, row = (c >> 3) & 127, arr = c >> 10;
        const __nv_bfloat16* src = (arr ? g_Flo : g_Fhi) + (size_t)(m0 + row) * ND + kc * 8;
        cp_async16(sA + arr * (128 * XA_SSTR) + row * XA_SSTR + kc * 8, src);
    }
    // W: 4096 chunks
    #pragma unroll
    for (int q = 0; q < 8; q++) {
        int c = tid + q * 512;
        int kc = c & 7, row = (c >> 3) & 255, arr = c >> 11;
        const __nv_bfloat16* src = (arr ? g_WxaTlo : g_WxaThi) + row * ND + kc * 8;
        cp_async16(sW + arr * (256 * XA_SSTR) + row * XA_SSTR + kc * 8, src);
    }
    asm volatile("cp.async.commit_group;\ncp.async.wait_group 0;\n");
    __syncthreads();

    const int warp_m = (wid & 3) * 32;
    const int warp_n = (wid >> 2) * 64;
    const int a_row_l = lane & 15;
    const int a_col_l = (lane >> 4) * 8;
    const int b_row_l = (lane & 7) + ((lane >> 4) << 3);
    const int b_col_l = ((lane >> 3) & 1) * 8;

    float acc[2][8][4];
    #pragma unroll
    for (int mi = 0; mi < 2; mi++)
        #pragma unroll
        for (int nt = 0; nt < 8; nt++)
            #pragma unroll
            for (int c = 0; c < 4; c++) acc[mi][nt][c] = 0.f;

    #pragma unroll
    for (int ks = 0; ks < 4; ks++) {
        unsigned af[2][2][4];
        #pragma unroll
        for (int arr = 0; arr < 2; arr++)
            #pragma unroll
            for (int mi = 0; mi < 2; mi++)
                ldsm_x4(af[arr][mi],
                        sA + arr * (128 * XA_SSTR) +
                        (warp_m + mi * 16 + a_row_l) * XA_SSTR + ks * 16 + a_col_l);
        #pragma unroll
        for (int nj = 0; nj < 4; nj++) {
            unsigned bh[4], bl[4];
            ldsm_x4(bh, sW + (warp_n + nj * 16 + b_row_l) * XA_SSTR + ks * 16 + b_col_l);
            ldsm_x4(bl, sW + 256 * XA_SSTR + (warp_n + nj * 16 + b_row_l) * XA_SSTR + ks * 16 + b_col_l);
            #pragma unroll
            for (int mi = 0; mi < 2; mi++) {
                #pragma unroll
                for (int p = 0; p < 2; p++) {
                    float* c = acc[mi][nj * 2 + p];
                    MMA_BF16(c, af[0][mi], bh[p * 2], bh[p * 2 + 1]);
                    MMA_BF16(c, af[0][mi], bl[p * 2], bl[p * 2 + 1]);
                    MMA_BF16(c, af[1][mi], bh[p * 2], bh[p * 2 + 1]);
                }
            }
        }
    }

    const int g = lane >> 2, q2 = (lane & 3) * 2;
    #pragma unroll
    for (int mi = 0; mi < 2; mi++) {
        #pragma unroll
        for (int nt = 0; nt < 8; nt++) {
            int col = warp_n + nt * 8 + q2;
            int r0 = warp_m + mi * 16 + g;
            *reinterpret_cast<float2*>(&g_XA[(size_t)(m0 + r0) * NA + col]) =
                make_float2(acc[mi][nt][0], acc[mi][nt][1]);
            *reinterpret_cast<float2*>(&g_XA[(size_t)(m0 + r0 + 8) * NA + col]) =
                make_float2(acc[mi][nt][2], acc[mi][nt][3]);
        }
    }
}

// ---------------- fused attention: ha, beta, e, softmax(alpha) ----------------
__global__ void __launch_bounds__(1024) k_attn(const float* __restrict__ Wha,
                                               const float* __restrict__ Wb,
                                               const float* __restrict__ bb,
                                               const float* __restrict__ wa,
                                               float* __restrict__ out_alp,
                                               float* __restrict__ out_bet, int t) {
    __shared__ float hs[NH];
    __shared__ float pa[4][NA];
    __shared__ float pb[8][ND];
    __shared__ float ha_s[NA];
    __shared__ float wa_s[NA];
    __shared__ float e_s[NL];
    __shared__ float red[256];
    const int b = blockIdx.x, tid = threadIdx.x;

    hs[tid] = g_h[b * NH + tid];
    if (tid < NA) wa_s[tid] = wa[tid];
    __syncthreads();
    {
        int a = tid & 255, q = tid >> 8;
        int k0 = q * 256;
        float s = 0.f;
        #pragma unroll 16
        for (int k = 0; k < 256; k++) s += hs[k0 + k] * Wha[(size_t)(k0 + k) * NA + a];
        pa[q][a] = s;
    }
    if (tid < 512) {
        int d = tid & 63, q = tid >> 6;
        int k0 = q * 128;
        float s = 0.f;
        #pragma unroll 16
        for (int k = 0; k < 128; k++) s += hs[k0 + k] * Wb[(size_t)(k0 + k) * ND + d];
        pb[q][d] = s;
    }
    __syncthreads();
    if (tid < 256) {
        ha_s[tid] = pa[0][tid] + pa[1][tid] + pa[2][tid] + pa[3][tid];
    } else if (tid < 320) {
        int d = tid - 256;
        float tot = bb[d];
        #pragma unroll
        for (int i = 0; i < 8; i++) tot += pb[i][d];
        float bt = sigmoidf_(tot);
        g_beta[b * ND + d] = bt;
        out_bet[(size_t)(b * NT + t) * ND + d] = bt;
    }
    __syncthreads();

    // e[l] = sum_a tanh(XA + ha) * wa  — one warp per l
    {
        const int w = tid >> 5, lane = tid & 31;
        const float* XAb = g_XA + (size_t)((b * NT + t) * NL) * NA;
        for (int l = w; l < NL; l += 32) {
            float s = 0.f;
            #pragma unroll
            for (int i = 0; i < 8; i++) {
                int a = lane + i * 32;
                s += tanhf(XAb[(size_t)l * NA + a] + ha_s[a]) * wa_s[a];
            }
            #pragma unroll
            for (int o = 16; o > 0; o >>= 1) s += __shfl_xor_sync(0xffffffffu, s, o);
            if (lane == 0) e_s[l] = s;
        }
    }
    __syncthreads();

    // softmax over NL (first 256 threads carry data; all threads hit barriers)
    float v = -1e30f;
    if (tid < NL) v = e_s[tid];
    if (tid < 256) red[tid] = v;
    __syncthreads();
    for (int s2 = 128; s2 > 0; s2 >>= 1) {
        if (tid < s2) red[tid] = fmaxf(red[tid], red[tid + s2]);
        __syncthreads();
    }
    float mx = red[0];
    __syncthreads();
    float ex = (tid < NL) ? expf(v - mx) : 0.f;
    if (tid < 256) red[tid] = ex;
    __syncthreads();
    for (int s2 = 128; s2 > 0; s2 >>= 1) {
        if (tid < s2) red[tid] += red[tid + s2];
        __syncthreads();
    }
    float denom = red[0];
    if (tid < NL) {
        float al = ex / denom;
        g_alpha[b * NL + tid] = al;
        out_alp[(size_t)(b * NT + t) * NL + tid] = al;
    }
}

// v = x*(1+alpha)*beta -> out_vis (fp32) + A hi/lo (bf16)
__global__ void k_v(const float* __restrict__ feat, float* __restrict__ out_vis, int t) {
    int idx = blockIdx.x * 256 + threadIdx.x; // B*R = 1105920 exactly
    int b = idx / NR, r = idx % NR;
    int l = r / ND, d = r % ND;
    float val = feat[(size_t)(b * NT + t) * NR + r] *
                (1.f + g_alpha[b * NL + l]) * g_beta[b * ND + d];
    out_vis[(size_t)(b * NT + t) * NR + r] = val;
    __nv_bfloat16 hi, lo;
    split_bf16(val, hi, lo);
    g_Ahi[b * NK + r] = hi;
    g_Alo[b * NK + r] = lo;
}

// ---------------- tensor-core GEMM: gp[z] = A[128,Kz] @ W[4096,Kz]^T ----------------
// hi/lo 3-pass. BM=128, BN=128, BK=32, 8 warps, ldmatrix.x4,
// 4-stage cp.async pipeline with ONE __syncthreads per iteration.
__global__ void __launch_bounds__(256) k_mma() {
    extern __shared__ __nv_bfloat16 smem[];

    const int tid = threadIdx.x;
    const int wid = tid >> 5, lane = tid & 31;
    const int warp_m = (wid & 3) * 32;
    const int warp_n = (wid >> 2) * 64;
    const int n0 = blockIdx.x * 128;
    const int z = blockIdx.y;
    const int kbase = z * KPER;

    auto issue = [&](int stage, int kt) {
        const int k0 = kbase + kt * BK;
        __nv_bfloat16* sA = smem + stage * STG_ELEMS;
        __nv_bfloat16* sW = sA + 2 * 128 * SSTR;
        #pragma unroll
        for (int q = 0; q < 4; q++) {
            int c = tid + q * 256;
            int row = c >> 3, kc = c & 3, arr = (c >> 2) & 1;
            const __nv_bfloat16* src = (arr ? g_Alo : g_Ahi) + (size_t)row * NK + k0 + kc * 8;
            cp_async16(sA + arr * (128 * SSTR) + row * SSTR + kc * 8, src);
        }
        #pragma unroll
        for (int q = 0; q < 4; q++) {
            int c = tid + q * 256;
            int row = c >> 3, kc = c & 3, arr = (c >> 2) & 1;
            const __nv_bfloat16* src = (arr ? g_Wlo : g_Whi) + (size_t)(n0 + row) * NK + k0 + kc * 8;
            cp_async16(sW + arr * (128 * SSTR) + row * SSTR + kc * 8, src);
        }
        asm volatile("cp.async.commit_group;\n");
    };

    float acc[2][8][4];
    #pragma unroll
    for (int mi = 0; mi < 2; mi++)
        #pragma unroll
        for (int nt = 0; nt < 8; nt++)
            #pragma unroll
            for (int c = 0; c < 4; c++) acc[mi][nt][c] = 0.f;

    issue(0, 0);
    issue(1, 1);

    const int a_row_l = lane & 15;
    const int a_col_l = (lane >> 4) * 8;
    const int b_row_l = (lane & 7) + ((lane >> 4) << 3);
    const int b_col_l = ((lane >> 3) & 1) * 8;

    for (int kt = 0; kt < NIT; kt++) {
        if (kt + 2 < NIT) {
            issue((kt + 2) & 3, kt + 2);
            asm volatile("cp.async.wait_group 2;\n");
        } else if (kt + 1 < NIT) {
            asm volatile("cp.async.wait_group 1;\n");
        } else {
            asm volatile("cp.async.wait_group 0;\n");
        }
        __syncthreads();

        const __nv_bfloat16* sA = smem + (kt & 3) * STG_ELEMS;
        const __nv_bfloat16* sW = sA + 2 * 128 * SSTR;

        #pragma unroll
        for (int ks = 0; ks < 2; ks++) {
            unsigned af[2][2][4];
            #pragma unroll
            for (int arr = 0; arr < 2; arr++)
                #pragma unroll
                for (int mi = 0; mi < 2; mi++)
                    ldsm_x4(af[arr][mi],
                            sA + arr * (128 * SSTR) +
                            (warp_m + mi * 16 + a_row_l) * SSTR + ks * 16 + a_col_l);
            #pragma unroll
            for (int nj = 0; nj < 4; nj++) {
                unsigned bh[4], bl[4];
                ldsm_x4(bh, sW + (warp_n + nj * 16 + b_row_l) * SSTR + ks * 16 + b_col_l);
                ldsm_x4(bl, sW + 128 * SSTR + (warp_n + nj * 16 + b_row_l) * SSTR + ks * 16 + b_col_l);
                #pragma unroll
                for (int mi = 0; mi < 2; mi++) {
                    #pragma unroll
                    for (int p = 0; p < 2; p++) {
                        float* c = acc[mi][nj * 2 + p];
                        MMA_BF16(c, af[0][mi], bh[p * 2], bh[p * 2 + 1]);
                        MMA_BF16(c, af[0][mi], bl[p * 2], bl[p * 2 + 1]);
                        MMA_BF16(c, af[1][mi], bh[p * 2], bh[p * 2 + 1]);
                    }
                }
            }
        }
    }

    // epilogue: store partials (no atomics -> deterministic)
    float* gp = g_gp[z];
    const int g = lane >> 2, q2 = (lane & 3) * 2;
    #pragma unroll
    for (int mi = 0; mi < 2; mi++) {
        #pragma unroll
        for (int nt = 0; nt < 8; nt++) {
            int col = n0 + warp_n + nt * 8 + q2;
            int r0 = warp_m + mi * 16 + g;
            if (r0 < NB)
                *reinterpret_cast<float2*>(&gp[(size_t)r0 * NG + col]) =
                    make_float2(acc[mi][nt][0], acc[mi][nt][1]);
            int r1 = r0 + 8;
            if (r1 < NB)
                *reinterpret_cast<float2*>(&gp[(size_t)r1 * NG + col]) =
                    make_float2(acc[mi][nt][2], acc[mi][nt][3]);
        }
    }
}

// LSTM pointwise update (sums K-split partials + biases)
__global__ void k_lstm(const float* __restrict__ b_ih, const float* __restrict__ b_hh,
                       float* __restrict__ out_hdd, int t) {
    int idx = blockIdx.x * 256 + threadIdx.x; // B*H = 122880 exactly
    int b = idx / NH, j = idx % NH;
    float gi = b_ih[j] + b_hh[j];
    float gf = b_ih[NH + j] + b_hh[NH + j];
    float gg = b_ih[2 * NH + j] + b_hh[2 * NH + j];
    float go = b_ih[3 * NH + j] + b_hh[3 * NH + j];
    #pragma unroll
    for (int z = 0; z < KSPLIT; z++) {
        const float* gp = g_gp[z] + (size_t)b * NG;
        gi += gp[j];
        gf += gp[NH + j];
        gg += gp[2 * NH + j];
        go += gp[3 * NH + j];
    }
    float c = sigmoidf_(gf) * g_c[idx] + sigmoidf_(gi) * tanhf(gg);
    float h = sigmoidf_(go) * tanhf(c);
    g_c[idx] = c;
    g_h[idx] = h;
    out_hdd[(size_t)(b * NT + t) * NH + j] = h;
    __nv_bfloat16 hi, lo;
    split_bf16(h, hi, lo);
    g_Ahi[b * NK + NR + j] = hi;
    g_Alo[b * NK + NR + j] = lo;
}

// ---------------- host launcher ----------------
extern "C" void kernel_launch(void* const* d_in, const int* in_sizes, int n_in,
                              void* d_out, int out_size) {
    const float* feature = (const float*)d_in[0];
    const float* Wh_w = (const float*)d_in[1];
    const float* Wh_b = (const float*)d_in[2];
    const float* Wc_w = (const float*)d_in[3];
    const float* Wc_b = (const float*)d_in[4];
    const float* Wxa = (const float*)d_in[5];
    const float* Wha = (const float*)d_in[6];
    const float* wa = (const float*)d_in[7];
    const float* Wb = (const float*)d_in[8];
    const float* bb = (const float*)d_in[9];
    const float* W_ih = (const float*)d_in[10];
    const float* W_hh = (const float*)d_in[11];
    const float* b_ih = (const float*)d_in[12];
    const float* b_hh = (const float*)d_in[13];

    float* out = (float*)d_out;
    float* out_vis = out;
    float* out_hdd = out_vis + (size_t)NB * NT * NR;
    float* out_alp = out_hdd + (size_t)NB * NT * NH;
    float* out_bet = out_alp + (size_t)NB * NT * NL;

    static int attr_done = 0;
    if (!attr_done) {
        cudaFuncSetAttribute(k_mma, cudaFuncAttributeMaxDynamicSharedMemorySize, SMEM_BYTES);
        cudaFuncSetAttribute(k_xa2, cudaFuncAttributeMaxDynamicSharedMemorySize, XA_SMEM);
        attr_done = 1;
    }

    // t-independent precompute
    k_f0<<<NB, ND>>>(feature);
    k_h0c0<<<dim3(NB, NH / 128), 128>>>(Wh_w, Wh_b, Wc_w, Wc_b);
    k_wsplit<<<(int)(((size_t)NG * NK) / 256), 256>>>(W_ih, W_hh);
    k_fsplit<<<(int)(((size_t)NB * NT * NL * ND) / 256), 256>>>(feature);
    k_wxat<<<ND, NA>>>(Wxa);
    k_xa2<<<(NB * NT * NL) / 128, 512, XA_SMEM>>>();

    for (int t = 0; t < NT; t++) {
        k_attn<<<NB, 1024>>>(Wha, Wb, bb, wa, out_alp, out_bet, t);
        k_v<<<(NB * NR) / 256, 256>>>(feature, out_vis, t);
        k_mma<<<dim3(NG / 128, KSPLIT), 256, SMEM_BYTES>>>();
        k_lstm<<<(NB * NH) / 256, 256>>>(b_ih, b_hh, out_hdd, t);
    }
}

// round 6
// speedup vs baseline: 3.8197x; 1.1735x over previous
#include <cuda_runtime.h>
#include <cuda_bf16.h>
#include <math.h>

// Problem dims
constexpr int NB = 120;
constexpr int NT = 20;
constexpr int NL = 144;
constexpr int ND = 64;
constexpr int NH = 1024;
constexpr int NA = 256;
constexpr int NR = NL * ND;     // 9216
constexpr int NG = 4 * NH;      // 4096
constexpr int NK = NR + NH;     // 10240 (concat v|h)

// Recurrent GEMM config
constexpr int KSPLIT = 8;
constexpr int KPER = NK / KSPLIT;   // 1280
constexpr int BK = 16;
constexpr int NIT = KPER / BK;      // 80
constexpr int SSTR = 24;            // padded smem row stride (bf16) ; (3r)%8 perm -> conflict-free
constexpr int STG_ELEMS = 2 * (128 * SSTR) + 2 * (128 * SSTR); // 12288 els
constexpr int NSTG = 4;
constexpr int SMEM_BYTES = NSTG * STG_ELEMS * 2;               // 98304 B

// XA GEMM config
constexpr int XA_SSTR = 72;
constexpr int XA_SMEM = (2 * 128 * XA_SSTR + 2 * 256 * XA_SSTR) * 2; // 110592 B

// -------- scratch (device globals; no runtime allocation) --------
__device__ float g_XA[(size_t)NB * NT * NL * NA]; // 354 MB: feature @ Wxa
__device__ float g_h0[NB * NH];
__device__ float g_c[NB * NH];
__device__ float g_f0[NB * ND];
__device__ float g_gp[KSPLIT][NB * NG];   // per-K-split GEMM partials
// bf16 hi/lo operands (.bss zero-init keeps pad rows zero)
__device__ __align__(16) __nv_bfloat16 g_Ahi[128 * NK];
__device__ __align__(16) __nv_bfloat16 g_Alo[128 * NK];
__device__ __align__(16) __nv_bfloat16 g_Whi[(size_t)NG * NK];
__device__ __align__(16) __nv_bfloat16 g_Wlo[(size_t)NG * NK];
__device__ __align__(16) __nv_bfloat16 g_WxaThi[NA * ND]; // Wxa^T [256][64]
__device__ __align__(16) __nv_bfloat16 g_WxaTlo[NA * ND];

__device__ __forceinline__ float sigmoidf_(float x) {
    return 1.f / (1.f + expf(-x));
}

__device__ __forceinline__ void split_bf16(float x, __nv_bfloat16& hi, __nv_bfloat16& lo) {
    hi = __float2bfloat16(x);
    lo = __float2bfloat16(x - __bfloat162float(hi));
}

__device__ __forceinline__ void cp_async16(void* smem_dst, const void* gmem_src) {
    unsigned sa = (unsigned)__cvta_generic_to_shared(smem_dst);
    asm volatile("cp.async.cg.shared.global [%0], [%1], 16;\n" :: "r"(sa), "l"(gmem_src));
}

__device__ __forceinline__ void ldsm_x4(unsigned* r, const __nv_bfloat16* p) {
    unsigned sa = (unsigned)__cvta_generic_to_shared(p);
    asm volatile("ldmatrix.sync.aligned.m8n8.x4.shared.b16 {%0,%1,%2,%3}, [%4];"
                 : "=r"(r[0]), "=r"(r[1]), "=r"(r[2]), "=r"(r[3]) : "r"(sa));
}

#define MMA_BF16(C, AV, B0, B1) \
    asm volatile( \
        "mma.sync.aligned.m16n8k16.row.col.f32.bf16.bf16.f32 " \
        "{%0,%1,%2,%3}, {%4,%5,%6,%7}, {%8,%9}, {%0,%1,%2,%3};\n" \
        : "+f"((C)[0]), "+f"((C)[1]), "+f"((C)[2]), "+f"((C)[3]) \
        : "r"((AV)[0]), "r"((AV)[1]), "r"((AV)[2]), "r"((AV)[3]), \
          "r"(B0), "r"(B1))

// ---------------- init: f0 = mean_l feature[b*T+0, l, :] ----------------
__global__ void k_f0(const float* __restrict__ feat) {
    int b = blockIdx.x, d = threadIdx.x; // 64 threads
    const float* p = feat + (size_t)b * NT * NL * ND;
    float s = 0.f;
    for (int l = 0; l < NL; l++) s += p[l * ND + d];
    g_f0[b * ND + d] = s * (1.f / NL);
}

// h0 = tanh(f0 @ Wh_w^T + Wh_b), c0 = tanh(f0 @ Wc_w^T + Wc_b)
__global__ void k_h0c0(const float* __restrict__ Wh_w, const float* __restrict__ Wh_b,
                       const float* __restrict__ Wc_w, const float* __restrict__ Wc_b) {
    __shared__ float fs[ND];
    int b = blockIdx.x;
    int j = blockIdx.y * 128 + threadIdx.x;
    if (threadIdx.x < ND) fs[threadIdx.x] = g_f0[b * ND + threadIdx.x];
    __syncthreads();
    float sh = Wh_b[j], sc = Wc_b[j];
    #pragma unroll 8
    for (int d = 0; d < ND; d++) {
        float x = fs[d];
        sh += x * Wh_w[j * ND + d];
        sc += x * Wc_w[j * ND + d];
    }
    float h = tanhf(sh);
    g_h0[b * NH + j] = h;
    g_c[b * NH + j] = tanhf(sc);
    __nv_bfloat16 hi, lo;
    split_bf16(h, hi, lo);
    g_Ahi[b * NK + NR + j] = hi;
    g_Alo[b * NK + NR + j] = lo;
}

// split W = [W_ih | W_hh] into bf16 hi/lo   [NG][NK]
__global__ void k_wsplit(const float* __restrict__ W_ih, const float* __restrict__ W_hh) {
    size_t idx = (size_t)blockIdx.x * 256 + threadIdx.x; // NG*NK exactly
    int n = (int)(idx / NK), k = (int)(idx % NK);
    float x = (k < NR) ? W_ih[(size_t)n * NR + k] : W_hh[(size_t)n * NH + (k - NR)];
    __nv_bfloat16 hi, lo;
    split_bf16(x, hi, lo);
    g_Whi[idx] = hi;
    g_Wlo[idx] = lo;
}

// transpose + split Wxa [64][256] -> WxaT [256][64]
__global__ void k_wxat(const float* __restrict__ Wxa) {
    int d = blockIdx.x, a = threadIdx.x; // 64 blocks x 256 threads
    __nv_bfloat16 hi, lo;
    split_bf16(Wxa[d * NA + a], hi, lo);
    g_WxaThi[a * ND + d] = hi;
    g_WxaTlo[a * ND + d] = lo;
}

// ---------------- XA = feature @ Wxa via tensor cores ----------------
// BM=128, BN=256 (full N), K=64; 512 threads; converts fp32 feature in-kernel.
__global__ void __launch_bounds__(512) k_xa2(const float* __restrict__ feat) {
    extern __shared__ __nv_bfloat16 xsm[];
    __nv_bfloat16* sA = xsm;                       // 2 arr x 128 x XA_SSTR
    __nv_bfloat16* sW = xsm + 2 * 128 * XA_SSTR;   // 2 arr x 256 x XA_SSTR

    const int tid = threadIdx.x;
    const int wid = tid >> 5, lane = tid & 31;
    const int m0 = blockIdx.x * 128;

    // W: 4096 chunks of 16B via cp.async
    #pragma unroll
    for (int q = 0; q < 8; q++) {
        int c = tid + q * 512;
        int kc = c & 7, row = (c >> 3) & 255, arr = c >> 11;
        const __nv_bfloat16* src = (arr ? g_WxaTlo : g_WxaThi) + row * ND + kc * 8;
        cp_async16(sW + arr * (256 * XA_SSTR) + row * XA_SSTR + kc * 8, src);
    }
    asm volatile("cp.async.commit_group;\n");

    // A: load fp32 feature, split to hi/lo bf16 smem (128x64 = 2048 float4)
    #pragma unroll
    for (int q = 0; q < 4; q++) {
        int i = tid + q * 512;
        int row = i >> 4, c4 = (i & 15) * 4;
        float4 f = *reinterpret_cast<const float4*>(feat + (size_t)(m0 + row) * ND + c4);
        __nv_bfloat16 h0, l0, h1, l1, h2, l2, h3, l3;
        split_bf16(f.x, h0, l0); split_bf16(f.y, h1, l1);
        split_bf16(f.z, h2, l2); split_bf16(f.w, h3, l3);
        __nv_bfloat162* ph = reinterpret_cast<__nv_bfloat162*>(sA + row * XA_SSTR + c4);
        __nv_bfloat162* pl = reinterpret_cast<__nv_bfloat162*>(sA + 128 * XA_SSTR + row * XA_SSTR + c4);
        ph[0] = __nv_bfloat162(h0, h1); ph[1] = __nv_bfloat162(h2, h3);
        pl[0] = __nv_bfloat162(l0, l1); pl[1] = __nv_bfloat162(l2, l3);
    }
    asm volatile("cp.async.wait_group 0;\n");
    __syncthreads();

    const int warp_m = (wid & 3) * 32;
    const int warp_n = (wid >> 2) * 64;
    const int a_row_l = lane & 15;
    const int a_col_l = (lane >> 4) * 8;
    const int b_row_l = (lane & 7) + ((lane >> 4) << 3);
    const int b_col_l = ((lane >> 3) & 1) * 8;

    float acc[2][8][4];
    #pragma unroll
    for (int mi = 0; mi < 2; mi++)
        #pragma unroll
        for (int nt = 0; nt < 8; nt++)
            #pragma unroll
            for (int c = 0; c < 4; c++) acc[mi][nt][c] = 0.f;

    #pragma unroll
    for (int ks = 0; ks < 4; ks++) {
        unsigned af[2][2][4];
        #pragma unroll
        for (int arr = 0; arr < 2; arr++)
            #pragma unroll
            for (int mi = 0; mi < 2; mi++)
                ldsm_x4(af[arr][mi],
                        sA + arr * (128 * XA_SSTR) +
                        (warp_m + mi * 16 + a_row_l) * XA_SSTR + ks * 16 + a_col_l);
        #pragma unroll
        for (int nj = 0; nj < 4; nj++) {
            unsigned bh[4], bl[4];
            ldsm_x4(bh, sW + (warp_n + nj * 16 + b_row_l) * XA_SSTR + ks * 16 + b_col_l);
            ldsm_x4(bl, sW + 256 * XA_SSTR + (warp_n + nj * 16 + b_row_l) * XA_SSTR + ks * 16 + b_col_l);
            #pragma unroll
            for (int mi = 0; mi < 2; mi++) {
                #pragma unroll
                for (int p = 0; p < 2; p++) {
                    float* c = acc[mi][nj * 2 + p];
                    MMA_BF16(c, af[0][mi], bh[p * 2], bh[p * 2 + 1]);
                    MMA_BF16(c, af[0][mi], bl[p * 2], bl[p * 2 + 1]);
                    MMA_BF16(c, af[1][mi], bh[p * 2], bh[p * 2 + 1]);
                }
            }
        }
    }

    const int g = lane >> 2, q2 = (lane & 3) * 2;
    #pragma unroll
    for (int mi = 0; mi < 2; mi++) {
        #pragma unroll
        for (int nt = 0; nt < 8; nt++) {
            int col = warp_n + nt * 8 + q2;
            int r0 = warp_m + mi * 16 + g;
            *reinterpret_cast<float2*>(&g_XA[(size_t)(m0 + r0) * NA + col]) =
                make_float2(acc[mi][nt][0], acc[mi][nt][1]);
            *reinterpret_cast<float2*>(&g_XA[(size_t)(m0 + r0 + 8) * NA + col]) =
                make_float2(acc[mi][nt][2], acc[mi][nt][3]);
        }
    }
}

// ---------------- fused per-step kernel: LSTM(t-1) + attention + v ----------------
__global__ void __launch_bounds__(1024) k_step(const float* __restrict__ Wha,
                                               const float* __restrict__ Wb,
                                               const float* __restrict__ bb,
                                               const float* __restrict__ wa,
                                               const float* __restrict__ b_ih,
                                               const float* __restrict__ b_hh,
                                               const float* __restrict__ feat,
                                               float* __restrict__ out_vis,
                                               float* __restrict__ out_alp,
                                               float* __restrict__ out_bet,
                                               float* __restrict__ out_hdd,
                                               int t) {
    __shared__ float hs[NH];
    __shared__ float pa[4][NA];
    __shared__ float pb[8][ND];
    __shared__ float ha_s[NA];
    __shared__ float wa_s[NA];
    __shared__ float e_s[NL];
    __shared__ float red[256];
    __shared__ float alpha_s[NL];
    __shared__ float beta_s[ND];
    const int b = blockIdx.x, tid = threadIdx.x;

    // ---- LSTM update for step t-1 (produces h_t) ----
    if (t > 0) {
        const int j = tid;
        float gi = b_ih[j] + b_hh[j];
        float gf = b_ih[NH + j] + b_hh[NH + j];
        float gg = b_ih[2 * NH + j] + b_hh[2 * NH + j];
        float go = b_ih[3 * NH + j] + b_hh[3 * NH + j];
        #pragma unroll
        for (int z = 0; z < KSPLIT; z++) {
            const float* gp = g_gp[z] + (size_t)b * NG;
            gi += gp[j];
            gf += gp[NH + j];
            gg += gp[2 * NH + j];
            go += gp[3 * NH + j];
        }
        float c = sigmoidf_(gf) * g_c[b * NH + j] + sigmoidf_(gi) * tanhf(gg);
        float h = sigmoidf_(go) * tanhf(c);
        g_c[b * NH + j] = c;
        hs[j] = h;
        out_hdd[(size_t)(b * NT + (t - 1)) * NH + j] = h;
        __nv_bfloat16 hi, lo;
        split_bf16(h, hi, lo);
        g_Ahi[b * NK + NR + j] = hi;
        g_Alo[b * NK + NR + j] = lo;
    } else {
        hs[tid] = g_h0[b * NH + tid];
    }
    if (tid < NA) wa_s[tid] = wa[tid];
    __syncthreads();

    // ---- ha = h @ Wha (4-way K split), beta = sigmoid(h @ Wb + bb) (8-way) ----
    {
        int a = tid & 255, q = tid >> 8;
        int k0 = q * 256;
        float s = 0.f;
        #pragma unroll 16
        for (int k = 0; k < 256; k++) s += hs[k0 + k] * Wha[(size_t)(k0 + k) * NA + a];
        pa[q][a] = s;
    }
    if (tid < 512) {
        int d = tid & 63, q = tid >> 6;
        int k0 = q * 128;
        float s = 0.f;
        #pragma unroll 16
        for (int k = 0; k < 128; k++) s += hs[k0 + k] * Wb[(size_t)(k0 + k) * ND + d];
        pb[q][d] = s;
    }
    __syncthreads();
    if (tid < 256) {
        ha_s[tid] = pa[0][tid] + pa[1][tid] + pa[2][tid] + pa[3][tid];
    } else if (tid < 320) {
        int d = tid - 256;
        float tot = bb[d];
        #pragma unroll
        for (int i = 0; i < 8; i++) tot += pb[i][d];
        float bt = sigmoidf_(tot);
        beta_s[d] = bt;
        out_bet[(size_t)(b * NT + t) * ND + d] = bt;
    }
    __syncthreads();

    // ---- e[l] = sum_a tanh(XA + ha) * wa : one warp per l ----
    {
        const int w = tid >> 5, lane = tid & 31;
        const float* XAb = g_XA + (size_t)((b * NT + t) * NL) * NA;
        for (int l = w; l < NL; l += 32) {
            float s = 0.f;
            #pragma unroll
            for (int i = 0; i < 8; i++) {
                int a = lane + i * 32;
                s += tanhf(XAb[(size_t)l * NA + a] + ha_s[a]) * wa_s[a];
            }
            #pragma unroll
            for (int o = 16; o > 0; o >>= 1) s += __shfl_xor_sync(0xffffffffu, s, o);
            if (lane == 0) e_s[l] = s;
        }
    }
    __syncthreads();

    // ---- softmax over NL ----
    float v = -1e30f;
    if (tid < NL) v = e_s[tid];
    if (tid < 256) red[tid] = v;
    __syncthreads();
    for (int s2 = 128; s2 > 0; s2 >>= 1) {
        if (tid < s2) red[tid] = fmaxf(red[tid], red[tid + s2]);
        __syncthreads();
    }
    float mx = red[0];
    __syncthreads();
    float ex = (tid < NL) ? expf(v - mx) : 0.f;
    if (tid < 256) red[tid] = ex;
    __syncthreads();
    for (int s2 = 128; s2 > 0; s2 >>= 1) {
        if (tid < s2) red[tid] += red[tid + s2];
        __syncthreads();
    }
    float denom = red[0];
    if (tid < NL) {
        float al = ex / denom;
        alpha_s[tid] = al;
        out_alp[(size_t)(b * NT + t) * NL + tid] = al;
    }
    __syncthreads();

    // ---- v = x*(1+alpha)*beta -> out_vis + A hi/lo ----
    {
        const float* fb = feat + (size_t)(b * NT + t) * NR;
        float* ob = out_vis + (size_t)(b * NT + t) * NR;
        __nv_bfloat16* ah = g_Ahi + (size_t)b * NK;
        __nv_bfloat16* al_ = g_Alo + (size_t)b * NK;
        #pragma unroll
        for (int q = 0; q < NR / 1024; q++) {
            int r = tid + q * 1024;
            int l = r >> 6, d = r & 63;
            float val = fb[r] * (1.f + alpha_s[l]) * beta_s[d];
            ob[r] = val;
            __nv_bfloat16 hi, lo;
            split_bf16(val, hi, lo);
            ah[r] = hi;
            al_[r] = lo;
        }
    }
}

// ---------------- tensor-core GEMM: gp[z] = A[128,Kz] @ W[4096,Kz]^T ----------------
// hi/lo 3-pass. BM=128, BN=128, BK=16, 8 warps, ldmatrix.x4,
// 4-stage cp.async, ONE sync per iter, 2 CTAs/SM.
__global__ void __launch_bounds__(256, 2) k_mma() {
    extern __shared__ __nv_bfloat16 smem[];

    const int tid = threadIdx.x;
    const int wid = tid >> 5, lane = tid & 31;
    const int warp_m = (wid & 3) * 32;
    const int warp_n = (wid >> 2) * 64;
    const int n0 = blockIdx.x * 128;
    const int z = blockIdx.y;
    const int kbase = z * KPER;

    // per iter: A 512 chunks + W 512 chunks of 16B; 4 per thread.
    auto issue = [&](int stage, int kt) {
        const int k0 = kbase + kt * BK;
        __nv_bfloat16* sA = smem + stage * STG_ELEMS;
        __nv_bfloat16* sW = sA + 2 * 128 * SSTR;
        {
            int c = tid, kc = c & 1, arr = (c >> 1) & 1, row = c >> 2; // rows 0..63
            const __nv_bfloat16* srcA = (arr ? g_Alo : g_Ahi) + (size_t)row * NK + k0 + kc * 8;
            cp_async16(sA + arr * (128 * SSTR) + row * SSTR + kc * 8, srcA);
            const __nv_bfloat16* srcA2 = (arr ? g_Alo : g_Ahi) + (size_t)(row + 64) * NK + k0 + kc * 8;
            cp_async16(sA + arr * (128 * SSTR) + (row + 64) * SSTR + kc * 8, srcA2);
            const __nv_bfloat16* srcW = (arr ? g_Wlo : g_Whi) + (size_t)(n0 + row) * NK + k0 + kc * 8;
            cp_async16(sW + arr * (128 * SSTR) + row * SSTR + kc * 8, srcW);
            const __nv_bfloat16* srcW2 = (arr ? g_Wlo : g_Whi) + (size_t)(n0 + row + 64) * NK + k0 + kc * 8;
            cp_async16(sW + arr * (128 * SSTR) + (row + 64) * SSTR + kc * 8, srcW2);
        }
        asm volatile("cp.async.commit_group;\n");
    };

    float acc[2][8][4];
    #pragma unroll
    for (int mi = 0; mi < 2; mi++)
        #pragma unroll
        for (int nt = 0; nt < 8; nt++)
            #pragma unroll
            for (int c = 0; c < 4; c++) acc[mi][nt][c] = 0.f;

    issue(0, 0);
    issue(1, 1);

    const int a_row_l = lane & 15;
    const int a_col_l = (lane >> 4) * 8;
    const int b_row_l = (lane & 7) + ((lane >> 4) << 3);
    const int b_col_l = ((lane >> 3) & 1) * 8;

    for (int kt = 0; kt < NIT; kt++) {
        if (kt + 2 < NIT) {
            issue((kt + 2) & 3, kt + 2);
            asm volatile("cp.async.wait_group 2;\n");
        } else if (kt + 1 < NIT) {
            asm volatile("cp.async.wait_group 1;\n");
        } else {
            asm volatile("cp.async.wait_group 0;\n");
        }
        __syncthreads();

        const __nv_bfloat16* sA = smem + (kt & 3) * STG_ELEMS;
        const __nv_bfloat16* sW = sA + 2 * 128 * SSTR;

        unsigned af[2][2][4];
        #pragma unroll
        for (int arr = 0; arr < 2; arr++)
            #pragma unroll
            for (int mi = 0; mi < 2; mi++)
                ldsm_x4(af[arr][mi],
                        sA + arr * (128 * SSTR) +
                        (warp_m + mi * 16 + a_row_l) * SSTR + a_col_l);
        #pragma unroll
        for (int nj = 0; nj < 4; nj++) {
            unsigned bh[4], bl[4];
            ldsm_x4(bh, sW + (warp_n + nj * 16 + b_row_l) * SSTR + b_col_l);
            ldsm_x4(bl, sW + 128 * SSTR + (warp_n + nj * 16 + b_row_l) * SSTR + b_col_l);
            #pragma unroll
            for (int mi = 0; mi < 2; mi++) {
                #pragma unroll
                for (int p = 0; p < 2; p++) {
                    float* c = acc[mi][nj * 2 + p];
                    MMA_BF16(c, af[0][mi], bh[p * 2], bh[p * 2 + 1]);
                    MMA_BF16(c, af[0][mi], bl[p * 2], bl[p * 2 + 1]);
                    MMA_BF16(c, af[1][mi], bh[p * 2], bh[p * 2 + 1]);
                }
            }
        }
    }

    // epilogue: store partials (no atomics -> deterministic)
    float* gp = g_gp[z];
    const int g = lane >> 2, q2 = (lane & 3) * 2;
    #pragma unroll
    for (int mi = 0; mi < 2; mi++) {
        #pragma unroll
        for (int nt = 0; nt < 8; nt++) {
            int col = n0 + warp_n + nt * 8 + q2;
            int r0 = warp_m + mi * 16 + g;
            if (r0 < NB)
                *reinterpret_cast<float2*>(&gp[(size_t)r0 * NG + col]) =
                    make_float2(acc[mi][nt][0], acc[mi][nt][1]);
            int r1 = r0 + 8;
            if (r1 < NB)
                *reinterpret_cast<float2*>(&gp[(size_t)r1 * NG + col]) =
                    make_float2(acc[mi][nt][2], acc[mi][nt][3]);
        }
    }
}

// final LSTM (t = NT-1): writes out_hdd only
__global__ void k_last(const float* __restrict__ b_ih, const float* __restrict__ b_hh,
                       float* __restrict__ out_hdd) {
    int idx = blockIdx.x * 256 + threadIdx.x; // B*H
    int b = idx / NH, j = idx % NH;
    float gi = b_ih[j] + b_hh[j];
    float gf = b_ih[NH + j] + b_hh[NH + j];
    float gg = b_ih[2 * NH + j] + b_hh[2 * NH + j];
    float go = b_ih[3 * NH + j] + b_hh[3 * NH + j];
    #pragma unroll
    for (int z = 0; z < KSPLIT; z++) {
        const float* gp = g_gp[z] + (size_t)b * NG;
        gi += gp[j];
        gf += gp[NH + j];
        gg += gp[2 * NH + j];
        go += gp[3 * NH + j];
    }
    float c = sigmoidf_(gf) * g_c[idx] + sigmoidf_(gi) * tanhf(gg);
    float h = sigmoidf_(go) * tanhf(c);
    out_hdd[(size_t)(b * NT + (NT - 1)) * NH + j] = h;
}

// ---------------- host launcher ----------------
extern "C" void kernel_launch(void* const* d_in, const int* in_sizes, int n_in,
                              void* d_out, int out_size) {
    const float* feature = (const float*)d_in[0];
    const float* Wh_w = (const float*)d_in[1];
    const float* Wh_b = (const float*)d_in[2];
    const float* Wc_w = (const float*)d_in[3];
    const float* Wc_b = (const float*)d_in[4];
    const float* Wxa = (const float*)d_in[5];
    const float* Wha = (const float*)d_in[6];
    const float* wa = (const float*)d_in[7];
    const float* Wb = (const float*)d_in[8];
    const float* bb = (const float*)d_in[9];
    const float* W_ih = (const float*)d_in[10];
    const float* W_hh = (const float*)d_in[11];
    const float* b_ih = (const float*)d_in[12];
    const float* b_hh = (const float*)d_in[13];

    float* out = (float*)d_out;
    float* out_vis = out;
    float* out_hdd = out_vis + (size_t)NB * NT * NR;
    float* out_alp = out_hdd + (size_t)NB * NT * NH;
    float* out_bet = out_alp + (size_t)NB * NT * NL;

    static int attr_done = 0;
    if (!attr_done) {
        cudaFuncSetAttribute(k_mma, cudaFuncAttributeMaxDynamicSharedMemorySize, SMEM_BYTES);
        cudaFuncSetAttribute(k_xa2, cudaFuncAttributeMaxDynamicSharedMemorySize, XA_SMEM);
        attr_done = 1;
    }

    // t-independent precompute
    k_f0<<<NB, ND>>>(feature);
    k_h0c0<<<dim3(NB, NH / 128), 128>>>(Wh_w, Wh_b, Wc_w, Wc_b);
    k_wsplit<<<(int)(((size_t)NG * NK) / 256), 256>>>(W_ih, W_hh);
    k_wxat<<<ND, NA>>>(Wxa);
    k_xa2<<<(NB * NT * NL) / 128, 512, XA_SMEM>>>(feature);

    for (int t = 0; t < NT; t++) {
        k_step<<<NB, 1024>>>(Wha, Wb, bb, wa, b_ih, b_hh, feature,
                             out_vis, out_alp, out_bet, out_hdd, t);
        k_mma<<<dim3(NG / 128, KSPLIT), 256, SMEM_BYTES>>>();
    }
    k_last<<<(NB * NH) / 256, 256>>>(b_ih, b_hh, out_hdd);
}

// round 10
// speedup vs baseline: 4.6589x; 1.2197x over previous
#include <cuda_runtime.h>
#include <cuda_bf16.h>
#include <cuda_fp16.h>
#include <math.h>
#include <stdint.h>

// Problem dims
constexpr int NB = 120;
constexpr int NT = 20;
constexpr int NL = 144;
constexpr int ND = 64;
constexpr int NH = 1024;
constexpr int NA = 256;
constexpr int NR = NL * ND;     // 9216
constexpr int NG = 4 * NH;      // 4096
constexpr int NK = NR + NH;     // 10240 (concat v|h)

// Recurrent GEMM config (fp16 2-pass)
constexpr int KSPLIT = 8;
constexpr int KPER = NK / KSPLIT;   // 1280
constexpr int BK = 16;
constexpr int NIT = KPER / BK;      // 80
constexpr int SSTR = 24;            // padded smem row stride (fp16 elems)
constexpr int STG_ELEMS = 3 * (128 * SSTR);   // A(1) + W(2) = 9216 els
constexpr int NSTG = 4;
constexpr int SMEM_BYTES = NSTG * STG_ELEMS * 2; // 73728 B

// XA GEMM config (unchanged bf16 3-pass)
constexpr int XA_SSTR = 72;
constexpr int XA_SMEM = (2 * 128 * XA_SSTR + 2 * 256 * XA_SSTR) * 2; // 110592 B

// -------- scratch (device globals; no runtime allocation) --------
__device__ float g_XA[(size_t)NB * NT * NL * NA]; // 354 MB: feature @ Wxa
__device__ float g_h0[NB * NH];
__device__ float g_c[NB * NH];
__device__ float g_f0[NB * ND];
__device__ float g_gp[KSPLIT][NB * NG];   // per-K-split GEMM partials
// fp16 operands for recurrent GEMM (.bss zero-init keeps pad rows zero)
__device__ __align__(16) __half g_Af[128 * NK];            // A single fp16
__device__ __align__(16) __half g_W16h[(size_t)NG * NK];   // W fp16 hi
__device__ __align__(16) __half g_W16l[(size_t)NG * NK];   // W fp16 lo
// bf16 hi/lo for XA prologue
__device__ __align__(16) __nv_bfloat16 g_WxaThi[NA * ND]; // Wxa^T [256][64]
__device__ __align__(16) __nv_bfloat16 g_WxaTlo[NA * ND];

__device__ __forceinline__ float sigmoidf_(float x) {
    return 1.f / (1.f + expf(-x));
}

__device__ __forceinline__ void split_bf16(float x, __nv_bfloat16& hi, __nv_bfloat16& lo) {
    hi = __float2bfloat16(x);
    lo = __float2bfloat16(x - __bfloat162float(hi));
}

__device__ __forceinline__ void split_half(float x, __half& hi, __half& lo) {
    hi = __float2half_rn(x);
    lo = __float2half_rn(x - __half2float(hi));
}

__device__ __forceinline__ void cp_async16(void* smem_dst, const void* gmem_src) {
    unsigned sa = (unsigned)__cvta_generic_to_shared(smem_dst);
    asm volatile("cp.async.cg.shared.global [%0], [%1], 16;\n" :: "r"(sa), "l"(gmem_src));
}

__device__ __forceinline__ void ldsm_x4_b(unsigned* r, const __nv_bfloat16* p) {
    unsigned sa = (unsigned)__cvta_generic_to_shared(p);
    asm volatile("ldmatrix.sync.aligned.m8n8.x4.shared.b16 {%0,%1,%2,%3}, [%4];"
                 : "=r"(r[0]), "=r"(r[1]), "=r"(r[2]), "=r"(r[3]) : "r"(sa));
}

__device__ __forceinline__ void ldsm_x4_h(unsigned* r, const __half* p) {
    unsigned sa = (unsigned)__cvta_generic_to_shared(p);
    asm volatile("ldmatrix.sync.aligned.m8n8.x4.shared.b16 {%0,%1,%2,%3}, [%4];"
                 : "=r"(r[0]), "=r"(r[1]), "=r"(r[2]), "=r"(r[3]) : "r"(sa));
}

#define MMA_BF16(C, AV, B0, B1) \
    asm volatile( \
        "mma.sync.aligned.m16n8k16.row.col.f32.bf16.bf16.f32 " \
        "{%0,%1,%2,%3}, {%4,%5,%6,%7}, {%8,%9}, {%0,%1,%2,%3};\n" \
        : "+f"((C)[0]), "+f"((C)[1]), "+f"((C)[2]), "+f"((C)[3]) \
        : "r"((AV)[0]), "r"((AV)[1]), "r"((AV)[2]), "r"((AV)[3]), \
          "r"(B0), "r"(B1))

#define MMA_F16(C, AV, B0, B1) \
    asm volatile( \
        "mma.sync.aligned.m16n8k16.row.col.f32.f16.f16.f32 " \
        "{%0,%1,%2,%3}, {%4,%5,%6,%7}, {%8,%9}, {%0,%1,%2,%3};\n" \
        : "+f"((C)[0]), "+f"((C)[1]), "+f"((C)[2]), "+f"((C)[3]) \
        : "r"((AV)[0]), "r"((AV)[1]), "r"((AV)[2]), "r"((AV)[3]), \
          "r"(B0), "r"(B1))

// ---------------- init: f0 = mean_l feature[b*T+0, l, :] ----------------
__global__ void k_f0(const float* __restrict__ feat) {
    int b = blockIdx.x, d = threadIdx.x; // 64 threads
    const float* p = feat + (size_t)b * NT * NL * ND;
    float s = 0.f;
    for (int l = 0; l < NL; l++) s += p[l * ND + d];
    g_f0[b * ND + d] = s * (1.f / NL);
}

// h0 = tanh(f0 @ Wh_w^T + Wh_b), c0 = tanh(f0 @ Wc_w^T + Wc_b)
__global__ void k_h0c0(const float* __restrict__ Wh_w, const float* __restrict__ Wh_b,
                       const float* __restrict__ Wc_w, const float* __restrict__ Wc_b) {
    __shared__ float fs[ND];
    int b = blockIdx.x;
    int j = blockIdx.y * 128 + threadIdx.x;
    if (threadIdx.x < ND) fs[threadIdx.x] = g_f0[b * ND + threadIdx.x];
    __syncthreads();
    float sh = Wh_b[j], sc = Wc_b[j];
    #pragma unroll 8
    for (int d = 0; d < ND; d++) {
        float x = fs[d];
        sh += x * Wh_w[j * ND + d];
        sc += x * Wc_w[j * ND + d];
    }
    float h = tanhf(sh);
    g_h0[b * NH + j] = h;
    g_c[b * NH + j] = tanhf(sc);
    g_Af[b * NK + NR + j] = __float2half_rn(h);
}

// split W = [W_ih | W_hh] into fp16 hi/lo   [NG][NK]
__global__ void k_wsplit(const float* __restrict__ W_ih, const float* __restrict__ W_hh) {
    size_t idx = (size_t)blockIdx.x * 256 + threadIdx.x; // NG*NK exactly
    int n = (int)(idx / NK), k = (int)(idx % NK);
    float x = (k < NR) ? W_ih[(size_t)n * NR + k] : W_hh[(size_t)n * NH + (k - NR)];
    __half hi, lo;
    split_half(x, hi, lo);
    g_W16h[idx] = hi;
    g_W16l[idx] = lo;
}

// transpose + split Wxa [64][256] -> WxaT [256][64]
__global__ void k_wxat(const float* __restrict__ Wxa) {
    int d = blockIdx.x, a = threadIdx.x; // 64 blocks x 256 threads
    __nv_bfloat16 hi, lo;
    split_bf16(Wxa[d * NA + a], hi, lo);
    g_WxaThi[a * ND + d] = hi;
    g_WxaTlo[a * ND + d] = lo;
}

// ---------------- XA = feature @ Wxa via tensor cores (bf16 3-pass HMMA) ----------------
__global__ void __launch_bounds__(512) k_xa2(const float* __restrict__ feat) {
    extern __shared__ __nv_bfloat16 xsm[];
    __nv_bfloat16* sA = xsm;                       // 2 arr x 128 x XA_SSTR
    __nv_bfloat16* sW = xsm + 2 * 128 * XA_SSTR;   // 2 arr x 256 x XA_SSTR

    const int tid = threadIdx.x;
    const int wid = tid >> 5, lane = tid & 31;
    const int m0 = blockIdx.x * 128;

    #pragma unroll
    for (int q = 0; q < 8; q++) {
        int c = tid + q * 512;
        int kc = c & 7, row = (c >> 3) & 255, arr = c >> 11;
        const __nv_bfloat16* src = (arr ? g_WxaTlo : g_WxaThi) + row * ND + kc * 8;
        cp_async16(sW + arr * (256 * XA_SSTR) + row * XA_SSTR + kc * 8, src);
    }
    asm volatile("cp.async.commit_group;\n");

    #pragma unroll
    for (int q = 0; q < 4; q++) {
        int i = tid + q * 512;
        int row = i >> 4, c4 = (i & 15) * 4;
        float4 f = *reinterpret_cast<const float4*>(feat + (size_t)(m0 + row) * ND + c4);
        __nv_bfloat16 h0, l0, h1, l1, h2, l2, h3, l3;
        split_bf16(f.x, h0, l0); split_bf16(f.y, h1, l1);
        split_bf16(f.z, h2, l2); split_bf16(f.w, h3, l3);
        __nv_bfloat162* ph = reinterpret_cast<__nv_bfloat162*>(sA + row * XA_SSTR + c4);
        __nv_bfloat162* pl = reinterpret_cast<__nv_bfloat162*>(sA + 128 * XA_SSTR + row * XA_SSTR + c4);
        ph[0] = __nv_bfloat162(h0, h1); ph[1] = __nv_bfloat162(h2, h3);
        pl[0] = __nv_bfloat162(l0, l1); pl[1] = __nv_bfloat162(l2, l3);
    }
    asm volatile("cp.async.wait_group 0;\n");
    __syncthreads();

    const int warp_m = (wid & 3) * 32;
    const int warp_n = (wid >> 2) * 64;
    const int a_row_l = lane & 15;
    const int a_col_l = (lane >> 4) * 8;
    const int b_row_l = (lane & 7) + ((lane >> 4) << 3);
    const int b_col_l = ((lane >> 3) & 1) * 8;

    float acc[2][8][4];
    #pragma unroll
    for (int mi = 0; mi < 2; mi++)
        #pragma unroll
        for (int nt = 0; nt < 8; nt++)
            #pragma unroll
            for (int c = 0; c < 4; c++) acc[mi][nt][c] = 0.f;

    #pragma unroll
    for (int ks = 0; ks < 4; ks++) {
        unsigned af[2][2][4];
        #pragma unroll
        for (int arr = 0; arr < 2; arr++)
            #pragma unroll
            for (int mi = 0; mi < 2; mi++)
                ldsm_x4_b(af[arr][mi],
                          sA + arr * (128 * XA_SSTR) +
                          (warp_m + mi * 16 + a_row_l) * XA_SSTR + ks * 16 + a_col_l);
        #pragma unroll
        for (int nj = 0; nj < 4; nj++) {
            unsigned bh[4], bl[4];
            ldsm_x4_b(bh, sW + (warp_n + nj * 16 + b_row_l) * XA_SSTR + ks * 16 + b_col_l);
            ldsm_x4_b(bl, sW + 256 * XA_SSTR + (warp_n + nj * 16 + b_row_l) * XA_SSTR + ks * 16 + b_col_l);
            #pragma unroll
            for (int mi = 0; mi < 2; mi++) {
                #pragma unroll
                for (int p = 0; p < 2; p++) {
                    float* c = acc[mi][nj * 2 + p];
                    MMA_BF16(c, af[0][mi], bh[p * 2], bh[p * 2 + 1]);
                    MMA_BF16(c, af[0][mi], bl[p * 2], bl[p * 2 + 1]);
                    MMA_BF16(c, af[1][mi], bh[p * 2], bh[p * 2 + 1]);
                }
            }
        }
    }

    const int g = lane >> 2, q2 = (lane & 3) * 2;
    #pragma unroll
    for (int mi = 0; mi < 2; mi++) {
        #pragma unroll
        for (int nt = 0; nt < 8; nt++) {
            int col = warp_n + nt * 8 + q2;
            int r0 = warp_m + mi * 16 + g;
            *reinterpret_cast<float2*>(&g_XA[(size_t)(m0 + r0) * NA + col]) =
                make_float2(acc[mi][nt][0], acc[mi][nt][1]);
            *reinterpret_cast<float2*>(&g_XA[(size_t)(m0 + r0 + 8) * NA + col]) =
                make_float2(acc[mi][nt][2], acc[mi][nt][3]);
        }
    }
}

// ---------------- fused per-step kernel: LSTM(t-1) + attention + v ----------------
__global__ void __launch_bounds__(1024) k_step(const float* __restrict__ Wha,
                                               const float* __restrict__ Wb,
                                               const float* __restrict__ bb,
                                               const float* __restrict__ wa,
                                               const float* __restrict__ b_ih,
                                               const float* __restrict__ b_hh,
                                               const float* __restrict__ feat,
                                               float* __restrict__ out_vis,
                                               float* __restrict__ out_alp,
                                               float* __restrict__ out_bet,
                                               float* __restrict__ out_hdd,
                                               int t) {
    __shared__ float hs[NH];
    __shared__ float pa[4][NA];
    __shared__ float pb[8][ND];
    __shared__ float ha_s[NA];
    __shared__ float wa_s[NA];
    __shared__ float e_s[NL];
    __shared__ float red[256];
    __shared__ float alpha_s[NL];
    __shared__ float beta_s[ND];
    const int b = blockIdx.x, tid = threadIdx.x;

    if (t > 0) {
        const int j = tid;
        float gi = b_ih[j] + b_hh[j];
        float gf = b_ih[NH + j] + b_hh[NH + j];
        float gg = b_ih[2 * NH + j] + b_hh[2 * NH + j];
        float go = b_ih[3 * NH + j] + b_hh[3 * NH + j];
        #pragma unroll
        for (int z = 0; z < KSPLIT; z++) {
            const float* gp = g_gp[z] + (size_t)b * NG;
            gi += gp[j];
            gf += gp[NH + j];
            gg += gp[2 * NH + j];
            go += gp[3 * NH + j];
        }
        float c = sigmoidf_(gf) * g_c[b * NH + j] + sigmoidf_(gi) * tanhf(gg);
        float h = sigmoidf_(go) * tanhf(c);
        g_c[b * NH + j] = c;
        hs[j] = h;
        out_hdd[(size_t)(b * NT + (t - 1)) * NH + j] = h;
        g_Af[b * NK + NR + j] = __float2half_rn(h);
    } else {
        hs[tid] = g_h0[b * NH + tid];
    }
    if (tid < NA) wa_s[tid] = wa[tid];
    __syncthreads();

    {
        int a = tid & 255, q = tid >> 8;
        int k0 = q * 256;
        float s = 0.f;
        #pragma unroll 16
        for (int k = 0; k < 256; k++) s += hs[k0 + k] * Wha[(size_t)(k0 + k) * NA + a];
        pa[q][a] = s;
    }
    if (tid < 512) {
        int d = tid & 63, q = tid >> 6;
        int k0 = q * 128;
        float s = 0.f;
        #pragma unroll 16
        for (int k = 0; k < 128; k++) s += hs[k0 + k] * Wb[(size_t)(k0 + k) * ND + d];
        pb[q][d] = s;
    }
    __syncthreads();
    if (tid < 256) {
        ha_s[tid] = pa[0][tid] + pa[1][tid] + pa[2][tid] + pa[3][tid];
    } else if (tid < 320) {
        int d = tid - 256;
        float tot = bb[d];
        #pragma unroll
        for (int i = 0; i < 8; i++) tot += pb[i][d];
        float bt = sigmoidf_(tot);
        beta_s[d] = bt;
        out_bet[(size_t)(b * NT + t) * ND + d] = bt;
    }
    __syncthreads();

    {
        const int w = tid >> 5, lane = tid & 31;
        const float* XAb = g_XA + (size_t)((b * NT + t) * NL) * NA;
        for (int l = w; l < NL; l += 32) {
            float s = 0.f;
            #pragma unroll
            for (int i = 0; i < 8; i++) {
                int a = lane + i * 32;
                s += tanhf(XAb[(size_t)l * NA + a] + ha_s[a]) * wa_s[a];
            }
            #pragma unroll
            for (int o = 16; o > 0; o >>= 1) s += __shfl_xor_sync(0xffffffffu, s, o);
            if (lane == 0) e_s[l] = s;
        }
    }
    __syncthreads();

    float v = -1e30f;
    if (tid < NL) v = e_s[tid];
    if (tid < 256) red[tid] = v;
    __syncthreads();
    for (int s2 = 128; s2 > 0; s2 >>= 1) {
        if (tid < s2) red[tid] = fmaxf(red[tid], red[tid + s2]);
        __syncthreads();
    }
    float mx = red[0];
    __syncthreads();
    float ex = (tid < NL) ? expf(v - mx) : 0.f;
    if (tid < 256) red[tid] = ex;
    __syncthreads();
    for (int s2 = 128; s2 > 0; s2 >>= 1) {
        if (tid < s2) red[tid] += red[tid + s2];
        __syncthreads();
    }
    float denom = red[0];
    if (tid < NL) {
        float al = ex / denom;
        alpha_s[tid] = al;
        out_alp[(size_t)(b * NT + t) * NL + tid] = al;
    }
    __syncthreads();

    {
        const float* fb = feat + (size_t)(b * NT + t) * NR;
        float* ob = out_vis + (size_t)(b * NT + t) * NR;
        __half* af = g_Af + (size_t)b * NK;
        #pragma unroll
        for (int q = 0; q < NR / 1024; q++) {
            int r = tid + q * 1024;
            int l = r >> 6, d = r & 63;
            float val = fb[r] * (1.f + alpha_s[l]) * beta_s[d];
            ob[r] = val;
            af[r] = __float2half_rn(val);
        }
    }
}

// ---------------- HMMA GEMM: gp[z] = A[128,Kz] @ W[4096,Kz]^T ----------------
// fp16 2-pass: acc = A*Whi + A*Wlo. BM=128, BN=128, BK=16, 8 warps,
// ldmatrix.x4, 4-stage cp.async, ONE sync per iter, 2 CTAs/SM.
__global__ void __launch_bounds__(256, 2) k_mma() {
    extern __shared__ __half smem[];

    const int tid = threadIdx.x;
    const int wid = tid >> 5, lane = tid & 31;
    const int warp_m = (wid & 3) * 32;
    const int warp_n = (wid >> 2) * 64;
    const int n0 = blockIdx.x * 128;
    const int z = blockIdx.y;
    const int kbase = z * KPER;

    // per iter: A 256 chunks + W 512 chunks of 16B; 3 per thread.
    auto issue = [&](int stage, int kt) {
        const int k0 = kbase + kt * BK;
        __half* sA = smem + stage * STG_ELEMS;
        __half* sW = sA + 128 * SSTR;
        {
            // A: 256 chunks: kc = tid&1, row = tid>>1
            int kc = tid & 1, row = tid >> 1;
            const __half* srcA = g_Af + (size_t)row * NK + k0 + kc * 8;
            cp_async16(sA + row * SSTR + kc * 8, srcA);
            // W: 512 chunks: c = tid + q*256; kc=c&1, arr=(c>>1)&1, row=c>>2 (+64 for q=1)
            #pragma unroll
            for (int q = 0; q < 2; q++) {
                int c = tid + q * 256;
                int wkc = c & 1, arr = (c >> 1) & 1, row2 = c >> 2;
                const __half* srcW = (arr ? g_W16l : g_W16h) + (size_t)(n0 + row2) * NK + k0 + wkc * 8;
                cp_async16(sW + arr * (128 * SSTR) + row2 * SSTR + wkc * 8, srcW);
            }
        }
        asm volatile("cp.async.commit_group;\n");
    };

    float acc[2][8][4];
    #pragma unroll
    for (int mi = 0; mi < 2; mi++)
        #pragma unroll
        for (int nt = 0; nt < 8; nt++)
            #pragma unroll
            for (int c = 0; c < 4; c++) acc[mi][nt][c] = 0.f;

    issue(0, 0);
    issue(1, 1);

    const int a_row_l = lane & 15;
    const int a_col_l = (lane >> 4) * 8;
    const int b_row_l = (lane & 7) + ((lane >> 4) << 3);
    const int b_col_l = ((lane >> 3) & 1) * 8;

    for (int kt = 0; kt < NIT; kt++) {
        if (kt + 2 < NIT) {
            issue((kt + 2) & 3, kt + 2);
            asm volatile("cp.async.wait_group 2;\n");
        } else if (kt + 1 < NIT) {
            asm volatile("cp.async.wait_group 1;\n");
        } else {
            asm volatile("cp.async.wait_group 0;\n");
        }
        __syncthreads();

        const __half* sA = smem + (kt & 3) * STG_ELEMS;
        const __half* sW = sA + 128 * SSTR;

        unsigned af[2][4];
        #pragma unroll
        for (int mi = 0; mi < 2; mi++)
            ldsm_x4_h(af[mi], sA + (warp_m + mi * 16 + a_row_l) * SSTR + a_col_l);
        #pragma unroll
        for (int nj = 0; nj < 4; nj++) {
            unsigned bh[4], bl[4];
            ldsm_x4_h(bh, sW + (warp_n + nj * 16 + b_row_l) * SSTR + b_col_l);
            ldsm_x4_h(bl, sW + 128 * SSTR + (warp_n + nj * 16 + b_row_l) * SSTR + b_col_l);
            #pragma unroll
            for (int mi = 0; mi < 2; mi++) {
                #pragma unroll
                for (int p = 0; p < 2; p++) {
                    float* c = acc[mi][nj * 2 + p];
                    MMA_F16(c, af[mi], bh[p * 2], bh[p * 2 + 1]);
                    MMA_F16(c, af[mi], bl[p * 2], bl[p * 2 + 1]);
                }
            }
        }
    }

    // epilogue: store partials (no atomics -> deterministic)
    float* gp = g_gp[z];
    const int g = lane >> 2, q2 = (lane & 3) * 2;
    #pragma unroll
    for (int mi = 0; mi < 2; mi++) {
        #pragma unroll
        for (int nt = 0; nt < 8; nt++) {
            int col = n0 + warp_n + nt * 8 + q2;
            int r0 = warp_m + mi * 16 + g;
            if (r0 < NB)
                *reinterpret_cast<float2*>(&gp[(size_t)r0 * NG + col]) =
                    make_float2(acc[mi][nt][0], acc[mi][nt][1]);
            int r1 = r0 + 8;
            if (r1 < NB)
                *reinterpret_cast<float2*>(&gp[(size_t)r1 * NG + col]) =
                    make_float2(acc[mi][nt][2], acc[mi][nt][3]);
        }
    }
}

// final LSTM (t = NT-1): writes out_hdd only
__global__ void k_last(const float* __restrict__ b_ih, const float* __restrict__ b_hh,
                       float* __restrict__ out_hdd) {
    int idx = blockIdx.x * 256 + threadIdx.x; // B*H
    int b = idx / NH, j = idx % NH;
    float gi = b_ih[j] + b_hh[j];
    float gf = b_ih[NH + j] + b_hh[NH + j];
    float gg = b_ih[2 * NH + j] + b_hh[2 * NH + j];
    float go = b_ih[3 * NH + j] + b_hh[3 * NH + j];
    #pragma unroll
    for (int z = 0; z < KSPLIT; z++) {
        const float* gp = g_gp[z] + (size_t)b * NG;
        gi += gp[j];
        gf += gp[NH + j];
        gg += gp[2 * NH + j];
        go += gp[3 * NH + j];
    }
    float c = sigmoidf_(gf) * g_c[idx] + sigmoidf_(gi) * tanhf(gg);
    float h = sigmoidf_(go) * tanhf(c);
    out_hdd[(size_t)(b * NT + (NT - 1)) * NH + j] = h;
}

// ---------------- host launcher ----------------
extern "C" void kernel_launch(void* const* d_in, const int* in_sizes, int n_in,
                              void* d_out, int out_size) {
    const float* feature = (const float*)d_in[0];
    const float* Wh_w = (const float*)d_in[1];
    const float* Wh_b = (const float*)d_in[2];
    const float* Wc_w = (const float*)d_in[3];
    const float* Wc_b = (const float*)d_in[4];
    const float* Wxa = (const float*)d_in[5];
    const float* Wha = (const float*)d_in[6];
    const float* wa = (const float*)d_in[7];
    const float* Wb = (const float*)d_in[8];
    const float* bb = (const float*)d_in[9];
    const float* W_ih = (const float*)d_in[10];
    const float* W_hh = (const float*)d_in[11];
    const float* b_ih = (const float*)d_in[12];
    const float* b_hh = (const float*)d_in[13];

    float* out = (float*)d_out;
    float* out_vis = out;
    float* out_hdd = out_vis + (size_t)NB * NT * NR;
    float* out_alp = out_hdd + (size_t)NB * NT * NH;
    float* out_bet = out_alp + (size_t)NB * NT * NL;

    static int attr_done = 0;
    if (!attr_done) {
        cudaFuncSetAttribute(k_mma, cudaFuncAttributeMaxDynamicSharedMemorySize, SMEM_BYTES);
        cudaFuncSetAttribute(k_xa2, cudaFuncAttributeMaxDynamicSharedMemorySize, XA_SMEM);
        attr_done = 1;
    }

    // t-independent precompute
    k_f0<<<NB, ND>>>(feature);
    k_h0c0<<<dim3(NB, NH / 128), 128>>>(Wh_w, Wh_b, Wc_w, Wc_b);
    k_wsplit<<<(int)(((size_t)NG * NK) / 256), 256>>>(W_ih, W_hh);
    k_wxat<<<ND, NA>>>(Wxa);
    k_xa2<<<(NB * NT * NL) / 128, 512, XA_SMEM>>>(feature);

    for (int t = 0; t < NT; t++) {
        k_step<<<NB, 1024>>>(Wha, Wb, bb, wa, b_ih, b_hh, feature,
                             out_vis, out_alp, out_bet, out_hdd, t);
        k_mma<<<dim3(NG / 128, KSPLIT), 256, SMEM_BYTES>>>();
    }
    k_last<<<(NB * NH) / 256, 256>>>(b_ih, b_hh, out_hdd);
}